// round 10
// baseline (speedup 1.0000x reference)
#include <cuda_runtime.h>
#include <cstdint>
#include <math.h>

// Problem constants
#define HID   4096
#define NB    4
#define QLEN  1024
#define NH    32
#define NKV   8
#define HD    128
#define PAST  1024
#define KVLEN 2048
#define MROWS (NB*QLEN)   // 4096
#define QSCALE 0.08838834764831845f
#define NEGBIG (-1.0e9f)

// GEMM tiling (unchanged from R8-passing kernel)
#define BM 128
#define BN 128
#define BK 16
#define NKITER (HID/BK)     // 256
#define SST 20
#define TILEF (BM*SST)
#define TILEB (TILEF*4)
#define GSMEM (4*TILEB)     // 40960 bytes

// Attention tiling
#define AQ  128
#define AKV 64
#define QST 132             // 528 B rows: 16B-aligned, 132 % 32 == 4 -> ldmatrix conflict-free
#define VST 68              // 272 B rows: 16B-aligned, 68 % 32 == 4  -> ldmatrix conflict-free
#define ATTN_SM_BYTES ((128*QST + 64*QST + 128*VST + 128*VST + 64) * 4)

// Scratch (device globals — allocation-free)
__device__ float g_q   [(size_t)NB*NH *QLEN*HD];   // [B,H,S,D]
__device__ float g_kn  [(size_t)NB*NKV*QLEN*HD];   // [B,Hkv,S,D]
__device__ float g_vn  [(size_t)NB*NKV*QLEN*HD];   // [B,Hkv,S,D]
__device__ float g_attn[(size_t)MROWS*HID];        // [B*S, H*D]

// ---------------------------------------------------------------------------
__device__ __forceinline__ float f2tf32(float x){
    uint32_t r; asm("cvt.rna.tf32.f32 %0, %1;" : "=r"(r) : "f"(x));
    return __uint_as_float(r);
}
__device__ __forceinline__ uint32_t smem_u32(const void* p){
    uint32_t a;
    asm("{ .reg .u64 t; cvta.to.shared.u64 t, %1; cvt.u32.u64 %0, t; }" : "=r"(a) : "l"(p));
    return a;
}
__device__ __forceinline__ void mma8(float* d, const uint32_t* a, const uint32_t* b){
    asm volatile(
        "mma.sync.aligned.m16n8k8.row.col.f32.tf32.tf32.f32 "
        "{%0,%1,%2,%3}, {%4,%5,%6,%7}, {%8,%9}, {%0,%1,%2,%3};"
        : "+f"(d[0]), "+f"(d[1]), "+f"(d[2]), "+f"(d[3])
        : "r"(a[0]), "r"(a[1]), "r"(a[2]), "r"(a[3]), "r"(b[0]), "r"(b[1]));
}
__device__ __forceinline__ void ldsm4(uint32_t addr, uint32_t& r0, uint32_t& r1,
                                      uint32_t& r2, uint32_t& r3){
    asm volatile("ldmatrix.sync.aligned.m8n8.x4.shared.b16 {%0,%1,%2,%3}, [%4];"
        : "=r"(r0), "=r"(r1), "=r"(r2), "=r"(r3) : "r"(addr));
}

// ---------------------------------------------------------------------------
// GEMM mainloop (unchanged from R8-passing kernel)
// ---------------------------------------------------------------------------
__device__ __forceinline__ void gemm_mainloop(
    const float* __restrict__ Ag, const float* __restrict__ Bg,
    float (&acc)[2][8][4])
{
    extern __shared__ float sm[];
    float* Abuf[2] = { sm,            sm + TILEF };
    float* Bbuf[2] = { sm + 2*TILEF,  sm + 3*TILEF };
    const uint32_t smbase = smem_u32(sm);

    const int tid  = threadIdx.x;
    const int lane = tid & 31;
    const int w    = tid >> 5;
    const int wm   = w & 3;
    const int wn   = w >> 2;

    #pragma unroll
    for (int mt = 0; mt < 2; mt++)
        #pragma unroll
        for (int nt = 0; nt < 8; nt++)
            #pragma unroll
            for (int c = 0; c < 4; c++) acc[mt][nt][c] = 0.f;

    const int arow = wm*32 + (lane & 7) + ((lane >> 3) & 1) * 8;
    const int acol = (lane >> 4) * 4;
    const uint32_t aoff = (uint32_t)(arow*SST + acol) * 4u;
    const int brow = wn*64 + (lane & 7) + (lane >> 4) * 8;
    const int bcol = ((lane >> 3) & 1) * 4;
    const uint32_t boff = (uint32_t)(brow*SST + bcol) * 4u;

    const int f0 = tid, f1 = 256 + tid;
    const int r0 = f0 >> 2, c0 = (f0 & 3) * 4;
    const int r1 = f1 >> 2, c1 = (f1 & 3) * 4;

    float4 ra[2], rb[2];
    auto ld_tile = [&](int k0){
        ra[0] = *reinterpret_cast<const float4*>(Ag + (size_t)r0*HID + k0 + c0);
        ra[1] = *reinterpret_cast<const float4*>(Ag + (size_t)r1*HID + k0 + c1);
        rb[0] = *reinterpret_cast<const float4*>(Bg + (size_t)r0*HID + k0 + c0);
        rb[1] = *reinterpret_cast<const float4*>(Bg + (size_t)r1*HID + k0 + c1);
    };
    auto st_tile = [&](float* As, float* Bs){
        float4 v;
        v.x=f2tf32(ra[0].x); v.y=f2tf32(ra[0].y); v.z=f2tf32(ra[0].z); v.w=f2tf32(ra[0].w);
        *reinterpret_cast<float4*>(As + r0*SST + c0) = v;
        v.x=f2tf32(ra[1].x); v.y=f2tf32(ra[1].y); v.z=f2tf32(ra[1].z); v.w=f2tf32(ra[1].w);
        *reinterpret_cast<float4*>(As + r1*SST + c1) = v;
        v.x=f2tf32(rb[0].x); v.y=f2tf32(rb[0].y); v.z=f2tf32(rb[0].z); v.w=f2tf32(rb[0].w);
        *reinterpret_cast<float4*>(Bs + r0*SST + c0) = v;
        v.x=f2tf32(rb[1].x); v.y=f2tf32(rb[1].y); v.z=f2tf32(rb[1].z); v.w=f2tf32(rb[1].w);
        *reinterpret_cast<float4*>(Bs + r1*SST + c1) = v;
    };

    ld_tile(0);
    st_tile(Abuf[0], Bbuf[0]);
    __syncthreads();

    for (int kt = 0; kt < NKITER; kt++) {
        const bool last = (kt == NKITER - 1);
        if (!last) ld_tile((kt + 1) * BK);

        const uint32_t Aaddr = smbase + (uint32_t)(kt & 1)*TILEB + aoff;
        const uint32_t Baddr = smbase + (uint32_t)(2 + (kt & 1))*TILEB + boff;
        #pragma unroll
        for (int ks = 0; ks < 2; ks++) {
            const uint32_t kkB = (uint32_t)(ks * 8) * 4u;
            uint32_t af[2][4], bf[8][2];
            ldsm4(Aaddr + kkB,                 af[0][0], af[0][1], af[0][2], af[0][3]);
            ldsm4(Aaddr + 16*SST*4 + kkB,      af[1][0], af[1][1], af[1][2], af[1][3]);
            #pragma unroll
            for (int p = 0; p < 4; p++)
                ldsm4(Baddr + (uint32_t)(p*16*SST)*4u + kkB,
                      bf[2*p][0], bf[2*p][1], bf[2*p+1][0], bf[2*p+1][1]);
            #pragma unroll
            for (int mt = 0; mt < 2; mt++)
                #pragma unroll
                for (int nt = 0; nt < 8; nt++)
                    mma8(acc[mt][nt], af[mt], bf[nt]);
        }
        if (!last) st_tile(Abuf[(kt+1) & 1], Bbuf[(kt+1) & 1]);
        __syncthreads();
    }
}

// ---------------------------------------------------------------------------
// QKV projection (unchanged)
// ---------------------------------------------------------------------------
__global__ void __launch_bounds__(256, 2) qkv_mma(
    const float* __restrict__ X,
    const float* __restrict__ Wq, const float* __restrict__ bq,
    const float* __restrict__ Wk, const float* __restrict__ bk,
    const float* __restrict__ Wv, const float* __restrict__ bv)
{
    const int m0  = blockIdx.x * BM;
    const int n0e = blockIdx.y * BN;
    const float* W; const float* bias; int sel, nl0;
    if (n0e < 4096)      { W = Wq; bias = bq; sel = 0; nl0 = n0e; }
    else if (n0e < 5120) { W = Wk; bias = bk; sel = 1; nl0 = n0e - 4096; }
    else                 { W = Wv; bias = bv; sel = 2; nl0 = n0e - 5120; }

    float acc[2][8][4];
    gemm_mainloop(X + (size_t)m0*HID, W + (size_t)nl0*HID, acc);

    const int lane = threadIdx.x & 31, w = threadIdx.x >> 5;
    const int wm = w & 3, wn = w >> 2;
    const int lq = lane >> 2, lr4 = lane & 3;

    #pragma unroll
    for (int mt = 0; mt < 2; mt++) {
        #pragma unroll
        for (int half = 0; half < 2; half++) {
            const int gm = m0 + wm*32 + mt*16 + lq + half*8;
            const int bb = gm >> 10, sq = gm & 1023;
            #pragma unroll
            for (int nt = 0; nt < 8; nt++) {
                const int nl = nl0 + wn*64 + nt*8 + lr4*2;
                const float2 bv2 = *reinterpret_cast<const float2*>(bias + nl);
                float2 v;
                v.x = acc[mt][nt][half*2 + 0] + bv2.x;
                v.y = acc[mt][nt][half*2 + 1] + bv2.y;
                const int h = nl >> 7, d = nl & 127;
                float* dst;
                if (sel == 0)      dst = &g_q [(((size_t)bb*NH  + h)*QLEN + sq)*HD + d];
                else if (sel == 1) dst = &g_kn[(((size_t)bb*NKV + h)*QLEN + sq)*HD + d];
                else               dst = &g_vn[(((size_t)bb*NKV + h)*QLEN + sq)*HD + d];
                *reinterpret_cast<float2*>(dst) = v;
            }
        }
    }
}

// ---------------------------------------------------------------------------
// Output projection (unchanged)
// ---------------------------------------------------------------------------
__global__ void __launch_bounds__(256, 2) out_mma(
    const float* __restrict__ Wo, const float* __restrict__ bo,
    float* __restrict__ out)
{
    const int m0 = blockIdx.x * BM;
    const int n0 = blockIdx.y * BN;

    float acc[2][8][4];
    gemm_mainloop(g_attn + (size_t)m0*HID, Wo + (size_t)n0*HID, acc);

    const int lane = threadIdx.x & 31, w = threadIdx.x >> 5;
    const int wm = w & 3, wn = w >> 2;
    const int lq = lane >> 2, lr4 = lane & 3;

    #pragma unroll
    for (int mt = 0; mt < 2; mt++) {
        #pragma unroll
        for (int half = 0; half < 2; half++) {
            const int gm = m0 + wm*32 + mt*16 + lq + half*8;
            #pragma unroll
            for (int nt = 0; nt < 8; nt++) {
                const int gn = n0 + wn*64 + nt*8 + lr4*2;
                const float2 bv2 = *reinterpret_cast<const float2*>(bo + gn);
                float2 v;
                v.x = acc[mt][nt][half*2 + 0] + bv2.x;
                v.y = acc[mt][nt][half*2 + 1] + bv2.y;
                *reinterpret_cast<float2*>(out + (size_t)gm*HID + gn) = v;
            }
        }
    }
}

// ---------------------------------------------------------------------------
// Flash attention on mma.sync tf32, fragment loads via ldmatrix.
// ---------------------------------------------------------------------------
__global__ void __launch_bounds__(256, 1) attn_mma(
    const float* __restrict__ pastK, const float* __restrict__ pastV,
    const int* __restrict__ amask)
{
    extern __shared__ float sm[];
    float* Qs = sm;                    // [128][QST]
    float* Ks = Qs + 128*QST;          // [64][QST]
    float* Vt = Ks + 64*QST;           // [128][VST] row d, col kv
    float* Ps = Vt + 128*VST;          // [128][VST] row q, col kv
    float* mb = Ps + 128*VST;          // [64]

    const uint32_t smQs = smem_u32(Qs);
    const uint32_t smKs = smem_u32(Ks);
    const uint32_t smVt = smem_u32(Vt);
    const uint32_t smPs = smem_u32(Ps);

    const int b = blockIdx.z, h = blockIdx.y, q0 = blockIdx.x * AQ;
    const int hkv = h >> 2;
    const int tid = threadIdx.x;
    const int lane = tid & 31, w = tid >> 5;
    const int lq = lane >> 2, lr4 = lane & 3;
    const int qrow = w*16 + lq;

    // ldmatrix per-lane base addresses (bytes)
    const int a_r = (lane & 7) + ((lane >> 3) & 1) * 8;
    const int a_c = (lane >> 4) * 4;
    const uint32_t qfrag = smQs + (uint32_t)((w*16 + a_r)*QST + a_c) * 4u;
    const uint32_t pfrag = smPs + (uint32_t)((w*16 + a_r)*VST + a_c) * 4u;
    const int b_r = (lane & 7) + (lane >> 4) * 8;
    const int b_c = ((lane >> 3) & 1) * 4;
    const uint32_t kfrag = smKs + (uint32_t)(b_r*QST + b_c) * 4u;
    const uint32_t vfrag = smVt + (uint32_t)(b_r*VST + b_c) * 4u;

    // Load Q tile [128][128]: pre-scaled, tf32-rounded
    {
        const int r = tid >> 1;
        const int cb = (tid & 1) * 64;
        const float* Qg = g_q + (((size_t)b*NH + h)*QLEN + q0 + r) * HD + cb;
        #pragma unroll
        for (int i = 0; i < 16; i++) {
            float4 q = *reinterpret_cast<const float4*>(Qg + i*4);
            float4 v;
            v.x = f2tf32(q.x * QSCALE); v.y = f2tf32(q.y * QSCALE);
            v.z = f2tf32(q.z * QSCALE); v.w = f2tf32(q.w * QSCALE);
            *reinterpret_cast<float4*>(Qs + r*QST + cb + i*4) = v;
        }
    }

    float oacc[16][4];
    #pragma unroll
    for (int d = 0; d < 16; d++)
        #pragma unroll
        for (int c = 0; c < 4; c++) oacc[d][c] = 0.f;
    float m0 = -3.0e38f, m1 = -3.0e38f, l0 = 0.f, l1 = 0.f;

    const float* Kgp = pastK + ((size_t)b*NKV + hkv) * PAST * HD;
    const float* Vgp = pastV + ((size_t)b*NKV + hkv) * PAST * HD;
    const float* Kgn = g_kn  + ((size_t)b*NKV + hkv) * QLEN * HD;
    const float* Vgn = g_vn  + ((size_t)b*NKV + hkv) * QLEN * HD;
    const int*   mg  = amask + (size_t)b * KVLEN;

    for (int kt = 0; kt < 32; kt++) {
        __syncthreads();
        {
            const int r = tid & 63, c4 = tid >> 6;
            const int p = kt*64 + r;
            const float* krow = (p < PAST) ? (Kgp + (size_t)p*HD) : (Kgn + (size_t)(p-PAST)*HD);
            const float* vrow = (p < PAST) ? (Vgp + (size_t)p*HD) : (Vgn + (size_t)(p-PAST)*HD);
            #pragma unroll
            for (int i = 0; i < 8; i++) {
                const int cc = (c4 + i*4) * 4;
                float4 k4 = *reinterpret_cast<const float4*>(krow + cc);
                float4 kv;
                kv.x = f2tf32(k4.x); kv.y = f2tf32(k4.y);
                kv.z = f2tf32(k4.z); kv.w = f2tf32(k4.w);
                *reinterpret_cast<float4*>(Ks + r*QST + cc) = kv;
                float4 v4 = *reinterpret_cast<const float4*>(vrow + cc);
                Vt[(cc+0)*VST + r] = f2tf32(v4.x);
                Vt[(cc+1)*VST + r] = f2tf32(v4.y);
                Vt[(cc+2)*VST + r] = f2tf32(v4.z);
                Vt[(cc+3)*VST + r] = f2tf32(v4.w);
            }
            if (tid < 64) mb[tid] = (mg[kt*64 + tid] == 0) ? 0.f : NEGBIG;
        }
        __syncthreads();

        // S = Q @ K^T  (16 k-steps, ldmatrix fragments)
        float sacc[8][4];
        #pragma unroll
        for (int nt = 0; nt < 8; nt++)
            #pragma unroll
            for (int c = 0; c < 4; c++) sacc[nt][c] = 0.f;
        #pragma unroll
        for (int ks = 0; ks < 16; ks++) {
            const uint32_t kkB = (uint32_t)ks * 32u;
            uint32_t af[4], bf[8][2];
            ldsm4(qfrag + kkB, af[0], af[1], af[2], af[3]);
            #pragma unroll
            for (int p = 0; p < 4; p++)
                ldsm4(kfrag + (uint32_t)(p*16*QST)*4u + kkB,
                      bf[2*p][0], bf[2*p][1], bf[2*p+1][0], bf[2*p+1][1]);
            #pragma unroll
            for (int nt = 0; nt < 8; nt++)
                mma8(sacc[nt], af, bf[nt]);
        }

        // mask bias + online softmax (rows qrow, qrow+8; quad = 4 lanes)
        float tmax0 = -3.0e38f, tmax1 = -3.0e38f;
        #pragma unroll
        for (int nt = 0; nt < 8; nt++) {
            const float b0 = mb[nt*8 + lr4*2], b1 = mb[nt*8 + lr4*2 + 1];
            sacc[nt][0] += b0; sacc[nt][1] += b1;
            sacc[nt][2] += b0; sacc[nt][3] += b1;
            tmax0 = fmaxf(tmax0, fmaxf(sacc[nt][0], sacc[nt][1]));
            tmax1 = fmaxf(tmax1, fmaxf(sacc[nt][2], sacc[nt][3]));
        }
        tmax0 = fmaxf(tmax0, __shfl_xor_sync(0xFFFFFFFFu, tmax0, 1));
        tmax0 = fmaxf(tmax0, __shfl_xor_sync(0xFFFFFFFFu, tmax0, 2));
        tmax1 = fmaxf(tmax1, __shfl_xor_sync(0xFFFFFFFFu, tmax1, 1));
        tmax1 = fmaxf(tmax1, __shfl_xor_sync(0xFFFFFFFFu, tmax1, 2));
        const float mn0 = fmaxf(m0, tmax0), mn1 = fmaxf(m1, tmax1);
        const float sc0 = __expf(m0 - mn0), sc1 = __expf(m1 - mn1);
        float sum0 = 0.f, sum1 = 0.f;
        #pragma unroll
        for (int nt = 0; nt < 8; nt++) {
            const float p00 = __expf(sacc[nt][0] - mn0);
            const float p01 = __expf(sacc[nt][1] - mn0);
            const float p10 = __expf(sacc[nt][2] - mn1);
            const float p11 = __expf(sacc[nt][3] - mn1);
            sum0 += p00 + p01; sum1 += p10 + p11;
            float2 s0; s0.x = f2tf32(p00); s0.y = f2tf32(p01);
            *reinterpret_cast<float2*>(Ps + qrow*VST + nt*8 + lr4*2) = s0;
            float2 s1; s1.x = f2tf32(p10); s1.y = f2tf32(p11);
            *reinterpret_cast<float2*>(Ps + (qrow+8)*VST + nt*8 + lr4*2) = s1;
        }
        sum0 += __shfl_xor_sync(0xFFFFFFFFu, sum0, 1);
        sum0 += __shfl_xor_sync(0xFFFFFFFFu, sum0, 2);
        sum1 += __shfl_xor_sync(0xFFFFFFFFu, sum1, 1);
        sum1 += __shfl_xor_sync(0xFFFFFFFFu, sum1, 2);
        l0 = l0*sc0 + sum0; l1 = l1*sc1 + sum1;
        m0 = mn0; m1 = mn1;
        #pragma unroll
        for (int d = 0; d < 16; d++) {
            oacc[d][0] *= sc0; oacc[d][1] *= sc0;
            oacc[d][2] *= sc1; oacc[d][3] *= sc1;
        }
        __syncwarp();                  // P stores visible to own warp's ldmatrix

        // O += P @ V  (8 k-steps, ldmatrix fragments)
        #pragma unroll
        for (int ks = 0; ks < 8; ks++) {
            const uint32_t kkB = (uint32_t)ks * 32u;
            uint32_t af[4];
            ldsm4(pfrag + kkB, af[0], af[1], af[2], af[3]);
            #pragma unroll
            for (int p = 0; p < 8; p++) {
                uint32_t bf0, bf1, bf2, bf3;
                ldsm4(vfrag + (uint32_t)(p*16*VST)*4u + kkB, bf0, bf1, bf2, bf3);
                uint32_t bfa[2] = { bf0, bf1 };
                uint32_t bfb[2] = { bf2, bf3 };
                mma8(oacc[2*p],     af, bfa);
                mma8(oacc[2*p + 1], af, bfb);
            }
        }
    }

    // normalize + write [B*S, H*D]
    const float inv0 = 1.f / l0, inv1 = 1.f / l1;
    float* orow0 = g_attn + ((size_t)(b*QLEN + q0 + w*16 + lq))*HID + h*HD;
    float* orow1 = orow0 + (size_t)8*HID;
    #pragma unroll
    for (int d = 0; d < 16; d++) {
        float2 v0; v0.x = oacc[d][0]*inv0; v0.y = oacc[d][1]*inv0;
        *reinterpret_cast<float2*>(orow0 + d*8 + lr4*2) = v0;
        float2 v1; v1.x = oacc[d][2]*inv1; v1.y = oacc[d][3]*inv1;
        *reinterpret_cast<float2*>(orow1 + d*8 + lr4*2) = v1;
    }
}

// ---------------------------------------------------------------------------
extern "C" void kernel_launch(void* const* d_in, const int* in_sizes, int n_in,
                              void* d_out, int out_size)
{
    const float* hs = (const float*)d_in[0];
    const float* pk = (const float*)d_in[1];
    const float* pv = (const float*)d_in[2];
    const int*   mk = (const int*)  d_in[3];
    const float* Wq = (const float*)d_in[4];
    const float* bq = (const float*)d_in[5];
    const float* Wk = (const float*)d_in[6];
    const float* bk = (const float*)d_in[7];
    const float* Wv = (const float*)d_in[8];
    const float* bv = (const float*)d_in[9];
    const float* Wo = (const float*)d_in[10];
    const float* bo = (const float*)d_in[11];
    float* out = (float*)d_out;

    cudaFuncSetAttribute(qkv_mma, cudaFuncAttributeMaxDynamicSharedMemorySize, GSMEM);
    cudaFuncSetAttribute(out_mma, cudaFuncAttributeMaxDynamicSharedMemorySize, GSMEM);
    cudaFuncSetAttribute(attn_mma, cudaFuncAttributeMaxDynamicSharedMemorySize, ATTN_SM_BYTES);

    dim3 g1(MROWS/BM, 6144/BN);           // 32 x 48
    qkv_mma<<<g1, 256, GSMEM>>>(hs, Wq, bq, Wk, bk, Wv, bv);

    dim3 g2(QLEN/AQ, NH, NB);             // 8 x 32 x 4
    attn_mma<<<g2, 256, ATTN_SM_BYTES>>>(pk, pv, mk);

    dim3 g3(MROWS/BM, HID/BN);            // 32 x 32
    out_mma<<<g3, 256, GSMEM>>>(Wo, bo, out);
}

// round 11
// speedup vs baseline: 1.1139x; 1.1139x over previous
#include <cuda_runtime.h>
#include <cstdint>
#include <math.h>

// Problem constants
#define HID   4096
#define NB    4
#define QLEN  1024
#define NH    32
#define NKV   8
#define HD    128
#define PAST  1024
#define KVLEN 2048
#define MROWS (NB*QLEN)   // 4096
#define QSCALE 0.08838834764831845f
#define NEGBIG (-1.0e9f)

// GEMM tiling: 128x128 CTA tile, BK=16, 8 warps (4x2), cp.async 4-stage pipeline
#define BM 128
#define BN 128
#define BK 16
#define NKITER (HID/BK)     // 256
#define SST 20              // smem row stride (floats); conflict-free, 80B rows (16B-aligned)
#define NSTAGE 4
#define STAGEF (256*SST)    // A rows 0..127, B rows 128..255
#define STAGEB (STAGEF*4)   // 20480 bytes
#define GSMEM (NSTAGE*STAGEB)   // 81920 bytes

// Attention tiling (R10-passing kernel)
#define AQ  128
#define AKV 64
#define QST 132
#define VST 68
#define ATTN_SM_BYTES ((128*QST + 64*QST + 128*VST + 128*VST + 64) * 4)

// Scratch (device globals — allocation-free)
__device__ float g_q   [(size_t)NB*NH *QLEN*HD];   // [B,H,S,D]
__device__ float g_kn  [(size_t)NB*NKV*QLEN*HD];
__device__ float g_vn  [(size_t)NB*NKV*QLEN*HD];
__device__ float g_attn[(size_t)MROWS*HID];        // tf32-rounded by attn epilogue
__device__ float g_x   [(size_t)MROWS*HID];        // tf32-rounded X
__device__ float g_wqkv[(size_t)6144*HID];         // tf32-rounded [Wq;Wk;Wv]
__device__ float g_wo  [(size_t)HID*HID];          // tf32-rounded Wo

// ---------------------------------------------------------------------------
__device__ __forceinline__ float f2tf32(float x){
    uint32_t r; asm("cvt.rna.tf32.f32 %0, %1;" : "=r"(r) : "f"(x));
    return __uint_as_float(r);
}
__device__ __forceinline__ uint32_t smem_u32(const void* p){
    uint32_t a;
    asm("{ .reg .u64 t; cvta.to.shared.u64 t, %1; cvt.u32.u64 %0, t; }" : "=r"(a) : "l"(p));
    return a;
}
__device__ __forceinline__ void mma8(float* d, const uint32_t* a, const uint32_t* b){
    asm volatile(
        "mma.sync.aligned.m16n8k8.row.col.f32.tf32.tf32.f32 "
        "{%0,%1,%2,%3}, {%4,%5,%6,%7}, {%8,%9}, {%0,%1,%2,%3};"
        : "+f"(d[0]), "+f"(d[1]), "+f"(d[2]), "+f"(d[3])
        : "r"(a[0]), "r"(a[1]), "r"(a[2]), "r"(a[3]), "r"(b[0]), "r"(b[1]));
}
__device__ __forceinline__ void ldsm4(uint32_t addr, uint32_t& r0, uint32_t& r1,
                                      uint32_t& r2, uint32_t& r3){
    asm volatile("ldmatrix.sync.aligned.m8n8.x4.shared.b16 {%0,%1,%2,%3}, [%4];"
        : "=r"(r0), "=r"(r1), "=r"(r2), "=r"(r3) : "r"(addr));
}
__device__ __forceinline__ void cpasync16(uint32_t dst, const void* src){
    asm volatile("cp.async.ca.shared.global [%0], [%1], 16;" :: "r"(dst), "l"(src));
}
#define CP_COMMIT() asm volatile("cp.async.commit_group;" ::: "memory")
#define CP_WAIT2()  asm volatile("cp.async.wait_group 2;" ::: "memory")

// ---------------------------------------------------------------------------
// One-time operand conversion: fp32 -> tf32(RNA) bits, stored as float.
// ---------------------------------------------------------------------------
__global__ void cvt_all(const float* __restrict__ X,
                        const float* __restrict__ Wq, const float* __restrict__ Wk,
                        const float* __restrict__ Wv, const float* __restrict__ Wo)
{
    const size_t nX  = (size_t)MROWS*HID/4;
    const size_t nWq = (size_t)HID*HID/4;
    const size_t nWk = (size_t)(NKV*HD)*HID/4;
    const size_t nTot = nX + nWq + 2*nWk + nWq;
    for (size_t i = blockIdx.x*(size_t)blockDim.x + threadIdx.x; i < nTot;
         i += (size_t)gridDim.x*blockDim.x) {
        const float4* src; float4* dst; size_t j = i;
        if (j < nX)              { src = (const float4*)X;  dst = (float4*)g_x; }
        else if ((j -= nX) < nWq){ src = (const float4*)Wq; dst = (float4*)g_wqkv; }
        else if ((j -= nWq) < nWk){ src = (const float4*)Wk; dst = (float4*)(g_wqkv + (size_t)4096*HID); }
        else if ((j -= nWk) < nWk){ src = (const float4*)Wv; dst = (float4*)(g_wqkv + (size_t)5120*HID); }
        else                     { j -= nWk; src = (const float4*)Wo; dst = (float4*)g_wo; }
        float4 v = src[j];
        v.x = f2tf32(v.x); v.y = f2tf32(v.y); v.z = f2tf32(v.z); v.w = f2tf32(v.w);
        dst[j] = v;
    }
}

// ---------------------------------------------------------------------------
// GEMM mainloop: cp.async 4-stage pipeline + ldmatrix fragments.
// Operands must already be tf32-rounded in global memory.
// ---------------------------------------------------------------------------
__device__ __forceinline__ void gemm_mainloop(
    const float* __restrict__ Ag, const float* __restrict__ Bg,
    float (&acc)[2][8][4])
{
    extern __shared__ float sm[];
    const uint32_t smbase = smem_u32(sm);

    const int tid  = threadIdx.x;
    const int lane = tid & 31;
    const int w    = tid >> 5;
    const int wm   = w & 3;
    const int wn   = w >> 2;

    #pragma unroll
    for (int mt = 0; mt < 2; mt++)
        #pragma unroll
        for (int nt = 0; nt < 8; nt++)
            #pragma unroll
            for (int c = 0; c < 4; c++) acc[mt][nt][c] = 0.f;

    // ldmatrix per-lane offsets (within a stage)
    const int arow = wm*32 + (lane & 7) + ((lane >> 3) & 1) * 8;
    const int acol = (lane >> 4) * 4;
    const uint32_t aoff = (uint32_t)(arow*SST + acol) * 4u;
    const int brow = wn*64 + (lane & 7) + (lane >> 4) * 8;
    const int bcol = ((lane >> 3) & 1) * 4;
    const uint32_t boff = (uint32_t)((128 + brow)*SST + bcol) * 4u;

    // cp.async staging: each thread copies 2 A-float4 and 2 B-float4 per stage
    const int r0 = tid >> 2, c0 = (tid & 3) * 4;

    auto issue_stage = [&](int s, int k0){
        const uint32_t base  = smbase + (uint32_t)s*STAGEB;
        cpasync16(base + (uint32_t)(r0*SST + c0)*4u,        Ag + (size_t)r0*HID + k0 + c0);
        cpasync16(base + (uint32_t)((r0+64)*SST + c0)*4u,   Ag + (size_t)(r0+64)*HID + k0 + c0);
        const uint32_t bb = base + (uint32_t)(128*SST)*4u;
        cpasync16(bb + (uint32_t)(r0*SST + c0)*4u,          Bg + (size_t)r0*HID + k0 + c0);
        cpasync16(bb + (uint32_t)((r0+64)*SST + c0)*4u,     Bg + (size_t)(r0+64)*HID + k0 + c0);
    };

    #pragma unroll
    for (int s = 0; s < NSTAGE-1; s++) { issue_stage(s, s*BK); CP_COMMIT(); }

    for (int kt = 0; kt < NKITER; kt++) {
        CP_WAIT2();
        __syncthreads();
        if (kt + NSTAGE-1 < NKITER) issue_stage((kt + NSTAGE-1) & 3, (kt + NSTAGE-1) * BK);
        CP_COMMIT();

        const uint32_t Sbase = smbase + (uint32_t)(kt & 3)*STAGEB;
        const uint32_t Aaddr = Sbase + aoff;
        const uint32_t Baddr = Sbase + boff;
        #pragma unroll
        for (int ks = 0; ks < 2; ks++) {
            const uint32_t kkB = (uint32_t)(ks * 8) * 4u;
            uint32_t af[2][4], bf[8][2];
            ldsm4(Aaddr + kkB,            af[0][0], af[0][1], af[0][2], af[0][3]);
            ldsm4(Aaddr + 16*SST*4 + kkB, af[1][0], af[1][1], af[1][2], af[1][3]);
            #pragma unroll
            for (int p = 0; p < 4; p++)
                ldsm4(Baddr + (uint32_t)(p*16*SST)*4u + kkB,
                      bf[2*p][0], bf[2*p][1], bf[2*p+1][0], bf[2*p+1][1]);
            #pragma unroll
            for (int mt = 0; mt < 2; mt++)
                #pragma unroll
                for (int nt = 0; nt < 8; nt++)
                    mma8(acc[mt][nt], af[mt], bf[nt]);
        }
    }
    __syncthreads();
}

// ---------------------------------------------------------------------------
// QKV projection: A = g_x, B = g_wqkv (pre-converted)
// ---------------------------------------------------------------------------
__global__ void __launch_bounds__(256, 2) qkv_mma(
    const float* __restrict__ bq, const float* __restrict__ bk,
    const float* __restrict__ bv)
{
    const int m0  = blockIdx.x * BM;
    const int n0e = blockIdx.y * BN;
    const float* bias; int sel, nl0;
    if (n0e < 4096)      { bias = bq; sel = 0; nl0 = n0e; }
    else if (n0e < 5120) { bias = bk; sel = 1; nl0 = n0e - 4096; }
    else                 { bias = bv; sel = 2; nl0 = n0e - 5120; }

    float acc[2][8][4];
    gemm_mainloop(g_x + (size_t)m0*HID, g_wqkv + (size_t)n0e*HID, acc);

    const int lane = threadIdx.x & 31, w = threadIdx.x >> 5;
    const int wm = w & 3, wn = w >> 2;
    const int lq = lane >> 2, lr4 = lane & 3;

    #pragma unroll
    for (int mt = 0; mt < 2; mt++) {
        #pragma unroll
        for (int half = 0; half < 2; half++) {
            const int gm = m0 + wm*32 + mt*16 + lq + half*8;
            const int bb = gm >> 10, sq = gm & 1023;
            #pragma unroll
            for (int nt = 0; nt < 8; nt++) {
                const int nl = nl0 + wn*64 + nt*8 + lr4*2;
                const float2 bv2 = *reinterpret_cast<const float2*>(bias + nl);
                float2 v;
                v.x = acc[mt][nt][half*2 + 0] + bv2.x;
                v.y = acc[mt][nt][half*2 + 1] + bv2.y;
                const int h = nl >> 7, d = nl & 127;
                float* dst;
                if (sel == 0)      dst = &g_q [(((size_t)bb*NH  + h)*QLEN + sq)*HD + d];
                else if (sel == 1) dst = &g_kn[(((size_t)bb*NKV + h)*QLEN + sq)*HD + d];
                else               dst = &g_vn[(((size_t)bb*NKV + h)*QLEN + sq)*HD + d];
                *reinterpret_cast<float2*>(dst) = v;
            }
        }
    }
}

// ---------------------------------------------------------------------------
// Output projection: A = g_attn (tf32-rounded by attn), B = g_wo
// ---------------------------------------------------------------------------
__global__ void __launch_bounds__(256, 2) out_mma(
    const float* __restrict__ bo, float* __restrict__ out)
{
    const int m0 = blockIdx.x * BM;
    const int n0 = blockIdx.y * BN;

    float acc[2][8][4];
    gemm_mainloop(g_attn + (size_t)m0*HID, g_wo + (size_t)n0*HID, acc);

    const int lane = threadIdx.x & 31, w = threadIdx.x >> 5;
    const int wm = w & 3, wn = w >> 2;
    const int lq = lane >> 2, lr4 = lane & 3;

    #pragma unroll
    for (int mt = 0; mt < 2; mt++) {
        #pragma unroll
        for (int half = 0; half < 2; half++) {
            const int gm = m0 + wm*32 + mt*16 + lq + half*8;
            #pragma unroll
            for (int nt = 0; nt < 8; nt++) {
                const int gn = n0 + wn*64 + nt*8 + lr4*2;
                const float2 bv2 = *reinterpret_cast<const float2*>(bo + gn);
                float2 v;
                v.x = acc[mt][nt][half*2 + 0] + bv2.x;
                v.y = acc[mt][nt][half*2 + 1] + bv2.y;
                *reinterpret_cast<float2*>(out + (size_t)gm*HID + gn) = v;
            }
        }
    }
}

// ---------------------------------------------------------------------------
// Flash attention (R10-passing kernel; epilogue now writes tf32-rounded g_attn)
// ---------------------------------------------------------------------------
__global__ void __launch_bounds__(256, 1) attn_mma(
    const float* __restrict__ pastK, const float* __restrict__ pastV,
    const int* __restrict__ amask)
{
    extern __shared__ float sm[];
    float* Qs = sm;                    // [128][QST]
    float* Ks = Qs + 128*QST;          // [64][QST]
    float* Vt = Ks + 64*QST;           // [128][VST]
    float* Ps = Vt + 128*VST;          // [128][VST]
    float* mb = Ps + 128*VST;          // [64]

    const uint32_t smQs = smem_u32(Qs);
    const uint32_t smKs = smem_u32(Ks);
    const uint32_t smVt = smem_u32(Vt);
    const uint32_t smPs = smem_u32(Ps);

    const int b = blockIdx.z, h = blockIdx.y, q0 = blockIdx.x * AQ;
    const int hkv = h >> 2;
    const int tid = threadIdx.x;
    const int lane = tid & 31, w = tid >> 5;
    const int lq = lane >> 2, lr4 = lane & 3;
    const int qrow = w*16 + lq;

    const int a_r = (lane & 7) + ((lane >> 3) & 1) * 8;
    const int a_c = (lane >> 4) * 4;
    const uint32_t qfrag = smQs + (uint32_t)((w*16 + a_r)*QST + a_c) * 4u;
    const uint32_t pfrag = smPs + (uint32_t)((w*16 + a_r)*VST + a_c) * 4u;
    const int b_r = (lane & 7) + (lane >> 4) * 8;
    const int b_c = ((lane >> 3) & 1) * 4;
    const uint32_t kfrag = smKs + (uint32_t)(b_r*QST + b_c) * 4u;
    const uint32_t vfrag = smVt + (uint32_t)(b_r*VST + b_c) * 4u;

    {
        const int r = tid >> 1;
        const int cb = (tid & 1) * 64;
        const float* Qg = g_q + (((size_t)b*NH + h)*QLEN + q0 + r) * HD + cb;
        #pragma unroll
        for (int i = 0; i < 16; i++) {
            float4 q = *reinterpret_cast<const float4*>(Qg + i*4);
            float4 v;
            v.x = f2tf32(q.x * QSCALE); v.y = f2tf32(q.y * QSCALE);
            v.z = f2tf32(q.z * QSCALE); v.w = f2tf32(q.w * QSCALE);
            *reinterpret_cast<float4*>(Qs + r*QST + cb + i*4) = v;
        }
    }

    float oacc[16][4];
    #pragma unroll
    for (int d = 0; d < 16; d++)
        #pragma unroll
        for (int c = 0; c < 4; c++) oacc[d][c] = 0.f;
    float m0 = -3.0e38f, m1 = -3.0e38f, l0 = 0.f, l1 = 0.f;

    const float* Kgp = pastK + ((size_t)b*NKV + hkv) * PAST * HD;
    const float* Vgp = pastV + ((size_t)b*NKV + hkv) * PAST * HD;
    const float* Kgn = g_kn  + ((size_t)b*NKV + hkv) * QLEN * HD;
    const float* Vgn = g_vn  + ((size_t)b*NKV + hkv) * QLEN * HD;
    const int*   mg  = amask + (size_t)b * KVLEN;

    for (int kt = 0; kt < 32; kt++) {
        __syncthreads();
        {
            const int r = tid & 63, c4 = tid >> 6;
            const int p = kt*64 + r;
            const float* krow = (p < PAST) ? (Kgp + (size_t)p*HD) : (Kgn + (size_t)(p-PAST)*HD);
            const float* vrow = (p < PAST) ? (Vgp + (size_t)p*HD) : (Vgn + (size_t)(p-PAST)*HD);
            #pragma unroll
            for (int i = 0; i < 8; i++) {
                const int cc = (c4 + i*4) * 4;
                float4 k4 = *reinterpret_cast<const float4*>(krow + cc);
                float4 kv;
                kv.x = f2tf32(k4.x); kv.y = f2tf32(k4.y);
                kv.z = f2tf32(k4.z); kv.w = f2tf32(k4.w);
                *reinterpret_cast<float4*>(Ks + r*QST + cc) = kv;
                float4 v4 = *reinterpret_cast<const float4*>(vrow + cc);
                Vt[(cc+0)*VST + r] = f2tf32(v4.x);
                Vt[(cc+1)*VST + r] = f2tf32(v4.y);
                Vt[(cc+2)*VST + r] = f2tf32(v4.z);
                Vt[(cc+3)*VST + r] = f2tf32(v4.w);
            }
            if (tid < 64) mb[tid] = (mg[kt*64 + tid] == 0) ? 0.f : NEGBIG;
        }
        __syncthreads();

        float sacc[8][4];
        #pragma unroll
        for (int nt = 0; nt < 8; nt++)
            #pragma unroll
            for (int c = 0; c < 4; c++) sacc[nt][c] = 0.f;
        #pragma unroll
        for (int ks = 0; ks < 16; ks++) {
            const uint32_t kkB = (uint32_t)ks * 32u;
            uint32_t af[4], bf[8][2];
            ldsm4(qfrag + kkB, af[0], af[1], af[2], af[3]);
            #pragma unroll
            for (int p = 0; p < 4; p++)
                ldsm4(kfrag + (uint32_t)(p*16*QST)*4u + kkB,
                      bf[2*p][0], bf[2*p][1], bf[2*p+1][0], bf[2*p+1][1]);
            #pragma unroll
            for (int nt = 0; nt < 8; nt++)
                mma8(sacc[nt], af, bf[nt]);
        }

        float tmax0 = -3.0e38f, tmax1 = -3.0e38f;
        #pragma unroll
        for (int nt = 0; nt < 8; nt++) {
            const float b0 = mb[nt*8 + lr4*2], b1 = mb[nt*8 + lr4*2 + 1];
            sacc[nt][0] += b0; sacc[nt][1] += b1;
            sacc[nt][2] += b0; sacc[nt][3] += b1;
            tmax0 = fmaxf(tmax0, fmaxf(sacc[nt][0], sacc[nt][1]));
            tmax1 = fmaxf(tmax1, fmaxf(sacc[nt][2], sacc[nt][3]));
        }
        tmax0 = fmaxf(tmax0, __shfl_xor_sync(0xFFFFFFFFu, tmax0, 1));
        tmax0 = fmaxf(tmax0, __shfl_xor_sync(0xFFFFFFFFu, tmax0, 2));
        tmax1 = fmaxf(tmax1, __shfl_xor_sync(0xFFFFFFFFu, tmax1, 1));
        tmax1 = fmaxf(tmax1, __shfl_xor_sync(0xFFFFFFFFu, tmax1, 2));
        const float mn0 = fmaxf(m0, tmax0), mn1 = fmaxf(m1, tmax1);
        const float sc0 = __expf(m0 - mn0), sc1 = __expf(m1 - mn1);
        float sum0 = 0.f, sum1 = 0.f;
        #pragma unroll
        for (int nt = 0; nt < 8; nt++) {
            const float p00 = __expf(sacc[nt][0] - mn0);
            const float p01 = __expf(sacc[nt][1] - mn0);
            const float p10 = __expf(sacc[nt][2] - mn1);
            const float p11 = __expf(sacc[nt][3] - mn1);
            sum0 += p00 + p01; sum1 += p10 + p11;
            float2 s0; s0.x = f2tf32(p00); s0.y = f2tf32(p01);
            *reinterpret_cast<float2*>(Ps + qrow*VST + nt*8 + lr4*2) = s0;
            float2 s1; s1.x = f2tf32(p10); s1.y = f2tf32(p11);
            *reinterpret_cast<float2*>(Ps + (qrow+8)*VST + nt*8 + lr4*2) = s1;
        }
        sum0 += __shfl_xor_sync(0xFFFFFFFFu, sum0, 1);
        sum0 += __shfl_xor_sync(0xFFFFFFFFu, sum0, 2);
        sum1 += __shfl_xor_sync(0xFFFFFFFFu, sum1, 1);
        sum1 += __shfl_xor_sync(0xFFFFFFFFu, sum1, 2);
        l0 = l0*sc0 + sum0; l1 = l1*sc1 + sum1;
        m0 = mn0; m1 = mn1;
        #pragma unroll
        for (int d = 0; d < 16; d++) {
            oacc[d][0] *= sc0; oacc[d][1] *= sc0;
            oacc[d][2] *= sc1; oacc[d][3] *= sc1;
        }
        __syncwarp();

        #pragma unroll
        for (int ks = 0; ks < 8; ks++) {
            const uint32_t kkB = (uint32_t)ks * 32u;
            uint32_t af[4];
            ldsm4(pfrag + kkB, af[0], af[1], af[2], af[3]);
            #pragma unroll
            for (int p = 0; p < 8; p++) {
                uint32_t bf0, bf1, bf2, bf3;
                ldsm4(vfrag + (uint32_t)(p*16*VST)*4u + kkB, bf0, bf1, bf2, bf3);
                uint32_t bfa[2] = { bf0, bf1 };
                uint32_t bfb[2] = { bf2, bf3 };
                mma8(oacc[2*p],     af, bfa);
                mma8(oacc[2*p + 1], af, bfb);
            }
        }
    }

    // normalize + write [B*S, H*D], tf32-rounded (consumed verbatim by out_mma)
    const float inv0 = 1.f / l0, inv1 = 1.f / l1;
    float* orow0 = g_attn + ((size_t)(b*QLEN + q0 + w*16 + lq))*HID + h*HD;
    float* orow1 = orow0 + (size_t)8*HID;
    #pragma unroll
    for (int d = 0; d < 16; d++) {
        float2 v0; v0.x = f2tf32(oacc[d][0]*inv0); v0.y = f2tf32(oacc[d][1]*inv0);
        *reinterpret_cast<float2*>(orow0 + d*8 + lr4*2) = v0;
        float2 v1; v1.x = f2tf32(oacc[d][2]*inv1); v1.y = f2tf32(oacc[d][3]*inv1);
        *reinterpret_cast<float2*>(orow1 + d*8 + lr4*2) = v1;
    }
}

// ---------------------------------------------------------------------------
extern "C" void kernel_launch(void* const* d_in, const int* in_sizes, int n_in,
                              void* d_out, int out_size)
{
    const float* hs = (const float*)d_in[0];
    const float* pk = (const float*)d_in[1];
    const float* pv = (const float*)d_in[2];
    const int*   mk = (const int*)  d_in[3];
    const float* Wq = (const float*)d_in[4];
    const float* bq = (const float*)d_in[5];
    const float* Wk = (const float*)d_in[6];
    const float* bk = (const float*)d_in[7];
    const float* Wv = (const float*)d_in[8];
    const float* bv = (const float*)d_in[9];
    const float* Wo = (const float*)d_in[10];
    const float* bo = (const float*)d_in[11];
    float* out = (float*)d_out;

    cudaFuncSetAttribute(qkv_mma, cudaFuncAttributeMaxDynamicSharedMemorySize, GSMEM);
    cudaFuncSetAttribute(out_mma, cudaFuncAttributeMaxDynamicSharedMemorySize, GSMEM);
    cudaFuncSetAttribute(attn_mma, cudaFuncAttributeMaxDynamicSharedMemorySize, ATTN_SM_BYTES);

    cvt_all<<<2048, 256>>>(hs, Wq, Wk, Wv, Wo);

    dim3 g1(MROWS/BM, 6144/BN);           // 32 x 48
    qkv_mma<<<g1, 256, GSMEM>>>(bq, bk, bv);

    dim3 g2(QLEN/AQ, NH, NB);             // 8 x 32 x 4
    attn_mma<<<g2, 256, ATTN_SM_BYTES>>>(pk, pv, mk);

    dim3 g3(MROWS/BM, HID/BN);            // 32 x 32
    out_mma<<<g3, 256, GSMEM>>>(bo, out);
}

// round 14
// speedup vs baseline: 1.2513x; 1.1234x over previous
#include <cuda_runtime.h>
#include <cstdint>
#include <math.h>

// Problem constants
#define HID   4096
#define NB    4
#define QLEN  1024
#define NH    32
#define NKV   8
#define HD    128
#define PAST  1024
#define KVLEN 2048
#define MROWS (NB*QLEN)   // 4096
#define QSCALE 0.08838834764831845f
#define NEGBIG (-1.0e9f)

// GEMM tiling (unchanged from R11-passing kernel)
#define BM 128
#define BN 128
#define BK 16
#define NKITER (HID/BK)     // 256
#define SST 20
#define NSTAGE 4
#define STAGEF (256*SST)
#define STAGEB (STAGEF*4)   // 20480 bytes
#define GSMEM (NSTAGE*STAGEB)   // 81920 bytes

// Attention tiling
#define AQ  128
#define AKV 64
#define QST 132             // K/Q row stride (floats); ldmatrix conflict-free
#define VST 68              // V/P row stride
#define ATTN_SM_BYTES ((128*QST + 2*64*QST + 128*VST + 128*VST) * 4)   // 204800

// Scratch (device globals — allocation-free)
__device__ float g_q   [(size_t)NB*NH *QLEN*HD];     // [B,H,S,D] fp32
__device__ float g_kc  [(size_t)NB*NKV*KVLEN*HD];    // [B,Hkv,KV,D] tf32-rounded
__device__ float g_vt  [(size_t)NB*NKV*HD*KVLEN];    // [B,Hkv,D,KV] tf32-rounded (transposed)
__device__ float g_attn[(size_t)MROWS*HID];          // tf32-rounded by attn epilogue
__device__ float g_x   [(size_t)MROWS*HID];          // tf32-rounded X
__device__ float g_wqkv[(size_t)6144*HID];           // tf32-rounded [Wq;Wk;Wv]
__device__ float g_wo  [(size_t)HID*HID];            // tf32-rounded Wo

// ---------------------------------------------------------------------------
__device__ __forceinline__ float f2tf32(float x){
    uint32_t r; asm("cvt.rna.tf32.f32 %0, %1;" : "=r"(r) : "f"(x));
    return __uint_as_float(r);
}
__device__ __forceinline__ uint32_t smem_u32(const void* p){
    uint32_t a;
    asm("{ .reg .u64 t; cvta.to.shared.u64 t, %1; cvt.u32.u64 %0, t; }" : "=r"(a) : "l"(p));
    return a;
}
__device__ __forceinline__ void mma8(float* d, const uint32_t* a, const uint32_t* b){
    asm volatile(
        "mma.sync.aligned.m16n8k8.row.col.f32.tf32.tf32.f32 "
        "{%0,%1,%2,%3}, {%4,%5,%6,%7}, {%8,%9}, {%0,%1,%2,%3};"
        : "+f"(d[0]), "+f"(d[1]), "+f"(d[2]), "+f"(d[3])
        : "r"(a[0]), "r"(a[1]), "r"(a[2]), "r"(a[3]), "r"(b[0]), "r"(b[1]));
}
__device__ __forceinline__ void ldsm4(uint32_t addr, uint32_t& r0, uint32_t& r1,
                                      uint32_t& r2, uint32_t& r3){
    asm volatile("ldmatrix.sync.aligned.m8n8.x4.shared.b16 {%0,%1,%2,%3}, [%4];"
        : "=r"(r0), "=r"(r1), "=r"(r2), "=r"(r3) : "r"(addr));
}
__device__ __forceinline__ void cpasync16(uint32_t dst, const void* src){
    asm volatile("cp.async.ca.shared.global [%0], [%1], 16;" :: "r"(dst), "l"(src));
}
#define CP_COMMIT() asm volatile("cp.async.commit_group;" ::: "memory")
#define CP_WAIT0()  asm volatile("cp.async.wait_group 0;" ::: "memory")
#define CP_WAIT1()  asm volatile("cp.async.wait_group 1;" ::: "memory")
#define CP_WAIT2()  asm volatile("cp.async.wait_group 2;" ::: "memory")

// ---------------------------------------------------------------------------
// One-time operand conversion: fp32 -> tf32(RNA) bits. Also copies past K
// into the combined KV buffer (rows [0, PAST)).
// ---------------------------------------------------------------------------
__global__ void cvt_all(const float* __restrict__ X,
                        const float* __restrict__ Wq, const float* __restrict__ Wk,
                        const float* __restrict__ Wv, const float* __restrict__ Wo,
                        const float* __restrict__ pastK)
{
    const size_t nX  = (size_t)MROWS*HID/4;
    const size_t nWq = (size_t)HID*HID/4;
    const size_t nWk = (size_t)(NKV*HD)*HID/4;
    const size_t nKp = (size_t)NB*NKV*PAST*HD/4;
    const size_t nTot = nX + nWq + 2*nWk + nKp + nWq;
    for (size_t i = blockIdx.x*(size_t)blockDim.x + threadIdx.x; i < nTot;
         i += (size_t)gridDim.x*blockDim.x) {
        size_t j = i; const float4* s; float4* dp;
        if (j < nX)                { s = (const float4*)X + j;  dp = (float4*)g_x + j; }
        else if ((j -= nX) < nWq)  { s = (const float4*)Wq + j; dp = (float4*)g_wqkv + j; }
        else if ((j -= nWq) < nWk) { s = (const float4*)Wk + j; dp = (float4*)(g_wqkv + (size_t)4096*HID) + j; }
        else if ((j -= nWk) < nWk) { s = (const float4*)Wv + j; dp = (float4*)(g_wqkv + (size_t)5120*HID) + j; }
        else if ((j -= nWk) < nKp) {
            s = (const float4*)pastK + j;
            const size_t per = (size_t)PAST*HD/4;
            const size_t bh = j / per, rem = j - bh*per;
            dp = (float4*)g_kc + bh*((size_t)KVLEN*HD/4) + rem;
        }
        else                       { j -= nKp; s = (const float4*)Wo + j; dp = (float4*)g_wo + j; }
        float4 v = *s;
        v.x = f2tf32(v.x); v.y = f2tf32(v.y); v.z = f2tf32(v.z); v.w = f2tf32(v.w);
        *dp = v;
    }
}

// ---------------------------------------------------------------------------
// Past-V transpose (+tf32 round): [bh, kv, d] -> g_vt[bh, d, kv], 32x32 tiles.
// ---------------------------------------------------------------------------
__global__ void vtrans(const float* __restrict__ pastV)
{
    __shared__ float t[32][33];
    const int bh  = blockIdx.x;
    const int kv0 = blockIdx.y * 32;
    const int d0  = blockIdx.z * 32;
    const int tx = threadIdx.x & 31, ty = threadIdx.x >> 5;   // 32 x 8
    const float* src = pastV + ((size_t)bh*PAST + kv0)*HD + d0;
    #pragma unroll
    for (int i = 0; i < 4; i++)
        t[ty + i*8][tx] = f2tf32(src[(size_t)(ty + i*8)*HD + tx]);
    __syncthreads();
    float* dst = g_vt + ((size_t)bh*HD + d0)*KVLEN + kv0;
    #pragma unroll
    for (int i = 0; i < 4; i++)
        dst[(size_t)(ty + i*8)*KVLEN + tx] = t[tx][ty + i*8];
}

// ---------------------------------------------------------------------------
// GEMM mainloop (unchanged from R11-passing kernel)
// ---------------------------------------------------------------------------
__device__ __forceinline__ void gemm_mainloop(
    const float* __restrict__ Ag, const float* __restrict__ Bg,
    float (&acc)[2][8][4])
{
    extern __shared__ float sm[];
    const uint32_t smbase = smem_u32(sm);

    const int tid  = threadIdx.x;
    const int lane = tid & 31;
    const int w    = tid >> 5;
    const int wm   = w & 3;
    const int wn   = w >> 2;

    #pragma unroll
    for (int mt = 0; mt < 2; mt++)
        #pragma unroll
        for (int nt = 0; nt < 8; nt++)
            #pragma unroll
            for (int c = 0; c < 4; c++) acc[mt][nt][c] = 0.f;

    const int arow = wm*32 + (lane & 7) + ((lane >> 3) & 1) * 8;
    const int acol = (lane >> 4) * 4;
    const uint32_t aoff = (uint32_t)(arow*SST + acol) * 4u;
    const int brow = wn*64 + (lane & 7) + (lane >> 4) * 8;
    const int bcol = ((lane >> 3) & 1) * 4;
    const uint32_t boff = (uint32_t)((128 + brow)*SST + bcol) * 4u;

    const int r0 = tid >> 2, c0 = (tid & 3) * 4;

    auto issue_stage = [&](int s, int k0){
        const uint32_t base  = smbase + (uint32_t)s*STAGEB;
        cpasync16(base + (uint32_t)(r0*SST + c0)*4u,        Ag + (size_t)r0*HID + k0 + c0);
        cpasync16(base + (uint32_t)((r0+64)*SST + c0)*4u,   Ag + (size_t)(r0+64)*HID + k0 + c0);
        const uint32_t bb = base + (uint32_t)(128*SST)*4u;
        cpasync16(bb + (uint32_t)(r0*SST + c0)*4u,          Bg + (size_t)r0*HID + k0 + c0);
        cpasync16(bb + (uint32_t)((r0+64)*SST + c0)*4u,     Bg + (size_t)(r0+64)*HID + k0 + c0);
    };

    #pragma unroll
    for (int s = 0; s < NSTAGE-1; s++) { issue_stage(s, s*BK); CP_COMMIT(); }

    for (int kt = 0; kt < NKITER; kt++) {
        CP_WAIT2();
        __syncthreads();
        if (kt + NSTAGE-1 < NKITER) issue_stage((kt + NSTAGE-1) & 3, (kt + NSTAGE-1) * BK);
        CP_COMMIT();

        const uint32_t Sbase = smbase + (uint32_t)(kt & 3)*STAGEB;
        const uint32_t Aaddr = Sbase + aoff;
        const uint32_t Baddr = Sbase + boff;
        #pragma unroll
        for (int ks = 0; ks < 2; ks++) {
            const uint32_t kkB = (uint32_t)(ks * 8) * 4u;
            uint32_t af[2][4], bf[8][2];
            ldsm4(Aaddr + kkB,            af[0][0], af[0][1], af[0][2], af[0][3]);
            ldsm4(Aaddr + 16*SST*4 + kkB, af[1][0], af[1][1], af[1][2], af[1][3]);
            #pragma unroll
            for (int p = 0; p < 4; p++)
                ldsm4(Baddr + (uint32_t)(p*16*SST)*4u + kkB,
                      bf[2*p][0], bf[2*p][1], bf[2*p+1][0], bf[2*p+1][1]);
            #pragma unroll
            for (int mt = 0; mt < 2; mt++)
                #pragma unroll
                for (int nt = 0; nt < 8; nt++)
                    mma8(acc[mt][nt], af[mt], bf[nt]);
        }
    }
    __syncthreads();
}

// ---------------------------------------------------------------------------
// QKV projection: A = g_x, B = g_wqkv (pre-converted).
// K/V epilogues write tf32-rounded into combined g_kc / transposed g_vt.
// ---------------------------------------------------------------------------
__global__ void __launch_bounds__(256, 2) qkv_mma(
    const float* __restrict__ bq, const float* __restrict__ bk,
    const float* __restrict__ bv)
{
    const int m0  = blockIdx.x * BM;
    const int n0e = blockIdx.y * BN;
    const float* bias; int sel, nl0;
    if (n0e < 4096)      { bias = bq; sel = 0; nl0 = n0e; }
    else if (n0e < 5120) { bias = bk; sel = 1; nl0 = n0e - 4096; }
    else                 { bias = bv; sel = 2; nl0 = n0e - 5120; }

    float acc[2][8][4];
    gemm_mainloop(g_x + (size_t)m0*HID, g_wqkv + (size_t)n0e*HID, acc);

    const int lane = threadIdx.x & 31, w = threadIdx.x >> 5;
    const int wm = w & 3, wn = w >> 2;
    const int lq = lane >> 2, lr4 = lane & 3;

    #pragma unroll
    for (int mt = 0; mt < 2; mt++) {
        #pragma unroll
        for (int half = 0; half < 2; half++) {
            const int gm = m0 + wm*32 + mt*16 + lq + half*8;
            const int bb = gm >> 10, sq = gm & 1023;
            #pragma unroll
            for (int nt = 0; nt < 8; nt++) {
                const int nl = nl0 + wn*64 + nt*8 + lr4*2;
                const float2 bv2 = *reinterpret_cast<const float2*>(bias + nl);
                float2 v;
                v.x = acc[mt][nt][half*2 + 0] + bv2.x;
                v.y = acc[mt][nt][half*2 + 1] + bv2.y;
                const int h = nl >> 7, d = nl & 127;
                if (sel == 0) {
                    float* dst = &g_q[(((size_t)bb*NH + h)*QLEN + sq)*HD + d];
                    *reinterpret_cast<float2*>(dst) = v;
                } else if (sel == 1) {
                    float2 vr; vr.x = f2tf32(v.x); vr.y = f2tf32(v.y);
                    float* dst = &g_kc[(((size_t)bb*NKV + h)*KVLEN + PAST + sq)*HD + d];
                    *reinterpret_cast<float2*>(dst) = vr;
                } else {
                    float* dst = &g_vt[(((size_t)bb*NKV + h)*HD + d)*(size_t)KVLEN + PAST + sq];
                    dst[0]     = f2tf32(v.x);
                    dst[KVLEN] = f2tf32(v.y);
                }
            }
        }
    }
}

// ---------------------------------------------------------------------------
// Output projection (unchanged)
// ---------------------------------------------------------------------------
__global__ void __launch_bounds__(256, 2) out_mma(
    const float* __restrict__ bo, float* __restrict__ out)
{
    const int m0 = blockIdx.x * BM;
    const int n0 = blockIdx.y * BN;

    float acc[2][8][4];
    gemm_mainloop(g_attn + (size_t)m0*HID, g_wo + (size_t)n0*HID, acc);

    const int lane = threadIdx.x & 31, w = threadIdx.x >> 5;
    const int wm = w & 3, wn = w >> 2;
    const int lq = lane >> 2, lr4 = lane & 3;

    #pragma unroll
    for (int mt = 0; mt < 2; mt++) {
        #pragma unroll
        for (int half = 0; half < 2; half++) {
            const int gm = m0 + wm*32 + mt*16 + lq + half*8;
            #pragma unroll
            for (int nt = 0; nt < 8; nt++) {
                const int gn = n0 + wn*64 + nt*8 + lr4*2;
                const float2 bv2 = *reinterpret_cast<const float2*>(bo + gn);
                float2 v;
                v.x = acc[mt][nt][half*2 + 0] + bv2.x;
                v.y = acc[mt][nt][half*2 + 1] + bv2.y;
                *reinterpret_cast<float2*>(out + (size_t)gm*HID + gn) = v;
            }
        }
    }
}

// ---------------------------------------------------------------------------
// Flash attention: cp.async pipelined K (double-buffered) + V (single, early
// issue), pre-converted/pre-transposed operands, ldmatrix fragments.
// ---------------------------------------------------------------------------
__global__ void __launch_bounds__(256, 1) attn_mma(
    const int* __restrict__ amask)
{
    extern __shared__ float sm[];
    float* Qs = sm;                    // [128][QST]
    float* Kb = Qs + 128*QST;          // [2][64][QST]
    float* Vb = Kb + 2*64*QST;         // [128][VST]
    float* Ps = Vb + 128*VST;          // [128][VST]

    const uint32_t smQs = smem_u32(Qs);
    const uint32_t smKb = smem_u32(Kb);
    const uint32_t smVb = smem_u32(Vb);
    const uint32_t smPs = smem_u32(Ps);

    const int b = blockIdx.z, h = blockIdx.y, q0 = blockIdx.x * AQ;
    const int hkv = h >> 2;
    const int tid = threadIdx.x;
    const int lane = tid & 31, w = tid >> 5;
    const int lq = lane >> 2, lr4 = lane & 3;
    const int qrow = w*16 + lq;

    const int a_r = (lane & 7) + ((lane >> 3) & 1) * 8;
    const int a_c = (lane >> 4) * 4;
    const uint32_t qfrag = smQs + (uint32_t)((w*16 + a_r)*QST + a_c) * 4u;
    const uint32_t pfrag = smPs + (uint32_t)((w*16 + a_r)*VST + a_c) * 4u;
    const int b_r = (lane & 7) + (lane >> 4) * 8;
    const int b_c = ((lane >> 3) & 1) * 4;
    const uint32_t kfrag0 = smKb + (uint32_t)(b_r*QST + b_c) * 4u;
    const uint32_t vfrag  = smVb + (uint32_t)(b_r*VST + b_c) * 4u;

    const float* Kg = g_kc + ((size_t)b*NKV + hkv)*(size_t)KVLEN*HD;
    const float* Vg = g_vt + ((size_t)b*NKV + hkv)*(size_t)HD*KVLEN;
    const int*   mg = amask + (size_t)b * KVLEN;

    auto issue_K = [&](int kt, int buf){
        const uint32_t base = smKb + (uint32_t)buf*(64*QST*4);
        const float* src = Kg + (size_t)kt*64*HD;
        #pragma unroll
        for (int i = 0; i < 8; i++){
            const int c = tid + i*256;
            const int row = c >> 5, col = (c & 31) * 4;
            cpasync16(base + (uint32_t)(row*QST + col)*4u, src + (size_t)row*HD + col);
        }
    };
    auto issue_V = [&](int kt){
        const float* src = Vg + kt*64;
        #pragma unroll
        for (int i = 0; i < 8; i++){
            const int c = tid + i*256;
            const int row = c >> 4, col = (c & 15) * 4;
            cpasync16(smVb + (uint32_t)(row*VST + col)*4u, src + (size_t)row*KVLEN + col);
        }
    };

    // prefetch K[0]; load Q (scaled + rounded) while it flies
    issue_K(0, 0); CP_COMMIT();
    {
        const int r = tid >> 1;
        const int cb = (tid & 1) * 64;
        const float* Qg = g_q + (((size_t)b*NH + h)*QLEN + q0 + r) * HD + cb;
        #pragma unroll
        for (int i = 0; i < 16; i++) {
            float4 q = *reinterpret_cast<const float4*>(Qg + i*4);
            float4 v;
            v.x = f2tf32(q.x * QSCALE); v.y = f2tf32(q.y * QSCALE);
            v.z = f2tf32(q.z * QSCALE); v.w = f2tf32(q.w * QSCALE);
            *reinterpret_cast<float4*>(Qs + r*QST + cb + i*4) = v;
        }
    }

    float oacc[16][4];
    #pragma unroll
    for (int d = 0; d < 16; d++)
        #pragma unroll
        for (int c = 0; c < 4; c++) oacc[d][c] = 0.f;
    float m0 = -3.0e38f, m1 = -3.0e38f, l0 = 0.f, l1 = 0.f;

    for (int kt = 0; kt < 32; kt++) {
        CP_WAIT0();                    // K[kt] arrived (only outstanding group)
        __syncthreads();               // K/Q visible; PV[kt-1] done -> Vb reusable
        issue_V(kt); CP_COMMIT();

        // S = Q @ K^T from Kb[kt&1]
        const uint32_t kfrag = kfrag0 + (uint32_t)(kt & 1)*(64*QST*4);
        float sacc[8][4];
        #pragma unroll
        for (int nt = 0; nt < 8; nt++)
            #pragma unroll
            for (int c = 0; c < 4; c++) sacc[nt][c] = 0.f;
        #pragma unroll
        for (int ks = 0; ks < 16; ks++) {
            const uint32_t kkB = (uint32_t)ks * 32u;
            uint32_t af[4], bf[8][2];
            ldsm4(qfrag + kkB, af[0], af[1], af[2], af[3]);
            #pragma unroll
            for (int p = 0; p < 4; p++)
                ldsm4(kfrag + (uint32_t)(p*16*QST)*4u + kkB,
                      bf[2*p][0], bf[2*p][1], bf[2*p+1][0], bf[2*p+1][1]);
            #pragma unroll
            for (int nt = 0; nt < 8; nt++)
                mma8(sacc[nt], af, bf[nt]);
        }

        if (kt < 31) { issue_K(kt+1, (kt+1) & 1); CP_COMMIT(); }

        // mask bias (direct from global, L1-resident) + online softmax
        float tmax0 = -3.0e38f, tmax1 = -3.0e38f;
        #pragma unroll
        for (int nt = 0; nt < 8; nt++) {
            const int ci = kt*64 + nt*8 + lr4*2;
            const float b0 = (mg[ci]   == 0) ? 0.f : NEGBIG;
            const float b1 = (mg[ci+1] == 0) ? 0.f : NEGBIG;
            sacc[nt][0] += b0; sacc[nt][1] += b1;
            sacc[nt][2] += b0; sacc[nt][3] += b1;
            tmax0 = fmaxf(tmax0, fmaxf(sacc[nt][0], sacc[nt][1]));
            tmax1 = fmaxf(tmax1, fmaxf(sacc[nt][2], sacc[nt][3]));
        }
        tmax0 = fmaxf(tmax0, __shfl_xor_sync(0xFFFFFFFFu, tmax0, 1));
        tmax0 = fmaxf(tmax0, __shfl_xor_sync(0xFFFFFFFFu, tmax0, 2));
        tmax1 = fmaxf(tmax1, __shfl_xor_sync(0xFFFFFFFFu, tmax1, 1));
        tmax1 = fmaxf(tmax1, __shfl_xor_sync(0xFFFFFFFFu, tmax1, 2));
        const float mn0 = fmaxf(m0, tmax0), mn1 = fmaxf(m1, tmax1);
        const float sc0 = __expf(m0 - mn0), sc1 = __expf(m1 - mn1);
        float sum0 = 0.f, sum1 = 0.f;
        #pragma unroll
        for (int nt = 0; nt < 8; nt++) {
            const float p00 = __expf(sacc[nt][0] - mn0);
            const float p01 = __expf(sacc[nt][1] - mn0);
            const float p10 = __expf(sacc[nt][2] - mn1);
            const float p11 = __expf(sacc[nt][3] - mn1);
            sum0 += p00 + p01; sum1 += p10 + p11;
            float2 s0; s0.x = f2tf32(p00); s0.y = f2tf32(p01);
            *reinterpret_cast<float2*>(Ps + qrow*VST + nt*8 + lr4*2) = s0;
            float2 s1; s1.x = f2tf32(p10); s1.y = f2tf32(p11);
            *reinterpret_cast<float2*>(Ps + (qrow+8)*VST + nt*8 + lr4*2) = s1;
        }
        sum0 += __shfl_xor_sync(0xFFFFFFFFu, sum0, 1);
        sum0 += __shfl_xor_sync(0xFFFFFFFFu, sum0, 2);
        sum1 += __shfl_xor_sync(0xFFFFFFFFu, sum1, 1);
        sum1 += __shfl_xor_sync(0xFFFFFFFFu, sum1, 2);
        l0 = l0*sc0 + sum0; l1 = l1*sc1 + sum1;
        m0 = mn0; m1 = mn1;
        #pragma unroll
        for (int d = 0; d < 16; d++) {
            oacc[d][0] *= sc0; oacc[d][1] *= sc0;
            oacc[d][2] *= sc1; oacc[d][3] *= sc1;
        }

        if (kt < 31) { CP_WAIT1(); } else { CP_WAIT0(); }   // V[kt] done
        __syncthreads();

        // O += P @ V
        #pragma unroll
        for (int ks = 0; ks < 8; ks++) {
            const uint32_t kkB = (uint32_t)ks * 32u;
            uint32_t af[4];
            ldsm4(pfrag + kkB, af[0], af[1], af[2], af[3]);
            #pragma unroll
            for (int p = 0; p < 8; p++) {
                uint32_t bf0, bf1, bf2, bf3;
                ldsm4(vfrag + (uint32_t)(p*16*VST)*4u + kkB, bf0, bf1, bf2, bf3);
                uint32_t bfa[2] = { bf0, bf1 };
                uint32_t bfb[2] = { bf2, bf3 };
                mma8(oacc[2*p],     af, bfa);
                mma8(oacc[2*p + 1], af, bfb);
            }
        }
    }

    // normalize + write [B*S, H*D], tf32-rounded (consumed verbatim by out_mma)
    const float inv0 = 1.f / l0, inv1 = 1.f / l1;
    float* orow0 = g_attn + ((size_t)(b*QLEN + q0 + w*16 + lq))*HID + h*HD;
    float* orow1 = orow0 + (size_t)8*HID;
    #pragma unroll
    for (int d = 0; d < 16; d++) {
        float2 v0; v0.x = f2tf32(oacc[d][0]*inv0); v0.y = f2tf32(oacc[d][1]*inv0);
        *reinterpret_cast<float2*>(orow0 + d*8 + lr4*2) = v0;
        float2 v1; v1.x = f2tf32(oacc[d][2]*inv1); v1.y = f2tf32(oacc[d][3]*inv1);
        *reinterpret_cast<float2*>(orow1 + d*8 + lr4*2) = v1;
    }
}

// ---------------------------------------------------------------------------
extern "C" void kernel_launch(void* const* d_in, const int* in_sizes, int n_in,
                              void* d_out, int out_size)
{
    const float* hs = (const float*)d_in[0];
    const float* pk = (const float*)d_in[1];
    const float* pv = (const float*)d_in[2];
    const int*   mk = (const int*)  d_in[3];
    const float* Wq = (const float*)d_in[4];
    const float* bq = (const float*)d_in[5];
    const float* Wk = (const float*)d_in[6];
    const float* bk = (const float*)d_in[7];
    const float* Wv = (const float*)d_in[8];
    const float* bv = (const float*)d_in[9];
    const float* Wo = (const float*)d_in[10];
    const float* bo = (const float*)d_in[11];
    float* out = (float*)d_out;

    cudaFuncSetAttribute(qkv_mma, cudaFuncAttributeMaxDynamicSharedMemorySize, GSMEM);
    cudaFuncSetAttribute(out_mma, cudaFuncAttributeMaxDynamicSharedMemorySize, GSMEM);
    cudaFuncSetAttribute(attn_mma, cudaFuncAttributeMaxDynamicSharedMemorySize, ATTN_SM_BYTES);

    cvt_all<<<2048, 256>>>(hs, Wq, Wk, Wv, Wo, pk);

    dim3 gv(NB*NKV, PAST/32, HD/32);      // 32 x 32 x 4
    vtrans<<<gv, 256>>>(pv);

    dim3 g1(MROWS/BM, 6144/BN);           // 32 x 48
    qkv_mma<<<g1, 256, GSMEM>>>(bq, bk, bv);

    dim3 g2(QLEN/AQ, NH, NB);             // 8 x 32 x 4
    attn_mma<<<g2, 256, ATTN_SM_BYTES>>>(mk);

    dim3 g3(MROWS/BM, HID/BN);            // 32 x 32
    out_mma<<<g3, 256, GSMEM>>>(bo, out);
}

// round 15
// speedup vs baseline: 1.3205x; 1.0553x over previous
#include <cuda_runtime.h>
#include <cstdint>
#include <math.h>

// Problem constants
#define HID   4096
#define NB    4
#define QLEN  1024
#define NH    32
#define NKV   8
#define HD    128
#define PAST  1024
#define KVLEN 2048
#define MROWS (NB*QLEN)   // 4096
#define QSCALE 0.08838834764831845f
#define NEGBIG (-1.0e9f)

// GEMM tiling (unchanged from R11/R14-passing kernel)
#define BM 128
#define BN 128
#define BK 16
#define NKITER (HID/BK)     // 256
#define SST 20
#define NSTAGE 4
#define STAGEF (256*SST)
#define STAGEB (STAGEF*4)   // 20480 bytes
#define GSMEM (NSTAGE*STAGEB)   // 81920 bytes

// Attention tiling: 128 threads, 64 q-rows/CTA, 2 CTAs/SM
#define AQ  64
#define AKV 64
#define QST 132             // K row stride (floats); ldmatrix conflict-free
#define VST 68              // V/P row stride
#define ATTN_SM_BYTES ((64*QST + 128*VST + 64*VST) * 4)   // 86016

// Scratch (device globals — allocation-free)
__device__ float g_q   [(size_t)NB*NH *QLEN*HD];     // [B,H,S,D] fp32
__device__ float g_kc  [(size_t)NB*NKV*KVLEN*HD];    // [B,Hkv,KV,D] tf32-rounded
__device__ float g_vt  [(size_t)NB*NKV*HD*KVLEN];    // [B,Hkv,D,KV] tf32-rounded (transposed)
__device__ float g_attn[(size_t)MROWS*HID];          // tf32-rounded by attn epilogue
__device__ float g_x   [(size_t)MROWS*HID];          // tf32-rounded X
__device__ float g_wqkv[(size_t)6144*HID];           // tf32-rounded [Wq;Wk;Wv]
__device__ float g_wo  [(size_t)HID*HID];            // tf32-rounded Wo

// ---------------------------------------------------------------------------
__device__ __forceinline__ float f2tf32(float x){
    uint32_t r; asm("cvt.rna.tf32.f32 %0, %1;" : "=r"(r) : "f"(x));
    return __uint_as_float(r);
}
__device__ __forceinline__ uint32_t smem_u32(const void* p){
    uint32_t a;
    asm("{ .reg .u64 t; cvta.to.shared.u64 t, %1; cvt.u32.u64 %0, t; }" : "=r"(a) : "l"(p));
    return a;
}
__device__ __forceinline__ void mma8(float* d, const uint32_t* a, const uint32_t* b){
    asm volatile(
        "mma.sync.aligned.m16n8k8.row.col.f32.tf32.tf32.f32 "
        "{%0,%1,%2,%3}, {%4,%5,%6,%7}, {%8,%9}, {%0,%1,%2,%3};"
        : "+f"(d[0]), "+f"(d[1]), "+f"(d[2]), "+f"(d[3])
        : "r"(a[0]), "r"(a[1]), "r"(a[2]), "r"(a[3]), "r"(b[0]), "r"(b[1]));
}
__device__ __forceinline__ void ldsm4(uint32_t addr, uint32_t& r0, uint32_t& r1,
                                      uint32_t& r2, uint32_t& r3){
    asm volatile("ldmatrix.sync.aligned.m8n8.x4.shared.b16 {%0,%1,%2,%3}, [%4];"
        : "=r"(r0), "=r"(r1), "=r"(r2), "=r"(r3) : "r"(addr));
}
__device__ __forceinline__ void cpasync16(uint32_t dst, const void* src){
    asm volatile("cp.async.ca.shared.global [%0], [%1], 16;" :: "r"(dst), "l"(src));
}
#define CP_COMMIT() asm volatile("cp.async.commit_group;" ::: "memory")
#define CP_WAIT0()  asm volatile("cp.async.wait_group 0;" ::: "memory")
#define CP_WAIT1()  asm volatile("cp.async.wait_group 1;" ::: "memory")
#define CP_WAIT2()  asm volatile("cp.async.wait_group 2;" ::: "memory")

// ---------------------------------------------------------------------------
// One-time operand conversion (unchanged from R14)
// ---------------------------------------------------------------------------
__global__ void cvt_all(const float* __restrict__ X,
                        const float* __restrict__ Wq, const float* __restrict__ Wk,
                        const float* __restrict__ Wv, const float* __restrict__ Wo,
                        const float* __restrict__ pastK)
{
    const size_t nX  = (size_t)MROWS*HID/4;
    const size_t nWq = (size_t)HID*HID/4;
    const size_t nWk = (size_t)(NKV*HD)*HID/4;
    const size_t nKp = (size_t)NB*NKV*PAST*HD/4;
    const size_t nTot = nX + nWq + 2*nWk + nKp + nWq;
    for (size_t i = blockIdx.x*(size_t)blockDim.x + threadIdx.x; i < nTot;
         i += (size_t)gridDim.x*blockDim.x) {
        size_t j = i; const float4* s; float4* dp;
        if (j < nX)                { s = (const float4*)X + j;  dp = (float4*)g_x + j; }
        else if ((j -= nX) < nWq)  { s = (const float4*)Wq + j; dp = (float4*)g_wqkv + j; }
        else if ((j -= nWq) < nWk) { s = (const float4*)Wk + j; dp = (float4*)(g_wqkv + (size_t)4096*HID) + j; }
        else if ((j -= nWk) < nWk) { s = (const float4*)Wv + j; dp = (float4*)(g_wqkv + (size_t)5120*HID) + j; }
        else if ((j -= nWk) < nKp) {
            s = (const float4*)pastK + j;
            const size_t per = (size_t)PAST*HD/4;
            const size_t bh = j / per, rem = j - bh*per;
            dp = (float4*)g_kc + bh*((size_t)KVLEN*HD/4) + rem;
        }
        else                       { j -= nKp; s = (const float4*)Wo + j; dp = (float4*)g_wo + j; }
        float4 v = *s;
        v.x = f2tf32(v.x); v.y = f2tf32(v.y); v.z = f2tf32(v.z); v.w = f2tf32(v.w);
        *dp = v;
    }
}

// ---------------------------------------------------------------------------
// Past-V transpose (unchanged from R14)
// ---------------------------------------------------------------------------
__global__ void vtrans(const float* __restrict__ pastV)
{
    __shared__ float t[32][33];
    const int bh  = blockIdx.x;
    const int kv0 = blockIdx.y * 32;
    const int d0  = blockIdx.z * 32;
    const int tx = threadIdx.x & 31, ty = threadIdx.x >> 5;
    const float* src = pastV + ((size_t)bh*PAST + kv0)*HD + d0;
    #pragma unroll
    for (int i = 0; i < 4; i++)
        t[ty + i*8][tx] = f2tf32(src[(size_t)(ty + i*8)*HD + tx]);
    __syncthreads();
    float* dst = g_vt + ((size_t)bh*HD + d0)*KVLEN + kv0;
    #pragma unroll
    for (int i = 0; i < 4; i++)
        dst[(size_t)(ty + i*8)*KVLEN + tx] = t[tx][ty + i*8];
}

// ---------------------------------------------------------------------------
// GEMM mainloop (unchanged from R11/R14-passing kernel)
// ---------------------------------------------------------------------------
__device__ __forceinline__ void gemm_mainloop(
    const float* __restrict__ Ag, const float* __restrict__ Bg,
    float (&acc)[2][8][4])
{
    extern __shared__ float sm[];
    const uint32_t smbase = smem_u32(sm);

    const int tid  = threadIdx.x;
    const int lane = tid & 31;
    const int w    = tid >> 5;
    const int wm   = w & 3;
    const int wn   = w >> 2;

    #pragma unroll
    for (int mt = 0; mt < 2; mt++)
        #pragma unroll
        for (int nt = 0; nt < 8; nt++)
            #pragma unroll
            for (int c = 0; c < 4; c++) acc[mt][nt][c] = 0.f;

    const int arow = wm*32 + (lane & 7) + ((lane >> 3) & 1) * 8;
    const int acol = (lane >> 4) * 4;
    const uint32_t aoff = (uint32_t)(arow*SST + acol) * 4u;
    const int brow = wn*64 + (lane & 7) + (lane >> 4) * 8;
    const int bcol = ((lane >> 3) & 1) * 4;
    const uint32_t boff = (uint32_t)((128 + brow)*SST + bcol) * 4u;

    const int r0 = tid >> 2, c0 = (tid & 3) * 4;

    auto issue_stage = [&](int s, int k0){
        const uint32_t base  = smbase + (uint32_t)s*STAGEB;
        cpasync16(base + (uint32_t)(r0*SST + c0)*4u,        Ag + (size_t)r0*HID + k0 + c0);
        cpasync16(base + (uint32_t)((r0+64)*SST + c0)*4u,   Ag + (size_t)(r0+64)*HID + k0 + c0);
        const uint32_t bb = base + (uint32_t)(128*SST)*4u;
        cpasync16(bb + (uint32_t)(r0*SST + c0)*4u,          Bg + (size_t)r0*HID + k0 + c0);
        cpasync16(bb + (uint32_t)((r0+64)*SST + c0)*4u,     Bg + (size_t)(r0+64)*HID + k0 + c0);
    };

    #pragma unroll
    for (int s = 0; s < NSTAGE-1; s++) { issue_stage(s, s*BK); CP_COMMIT(); }

    for (int kt = 0; kt < NKITER; kt++) {
        CP_WAIT2();
        __syncthreads();
        if (kt + NSTAGE-1 < NKITER) issue_stage((kt + NSTAGE-1) & 3, (kt + NSTAGE-1) * BK);
        CP_COMMIT();

        const uint32_t Sbase = smbase + (uint32_t)(kt & 3)*STAGEB;
        const uint32_t Aaddr = Sbase + aoff;
        const uint32_t Baddr = Sbase + boff;
        #pragma unroll
        for (int ks = 0; ks < 2; ks++) {
            const uint32_t kkB = (uint32_t)(ks * 8) * 4u;
            uint32_t af[2][4], bf[8][2];
            ldsm4(Aaddr + kkB,            af[0][0], af[0][1], af[0][2], af[0][3]);
            ldsm4(Aaddr + 16*SST*4 + kkB, af[1][0], af[1][1], af[1][2], af[1][3]);
            #pragma unroll
            for (int p = 0; p < 4; p++)
                ldsm4(Baddr + (uint32_t)(p*16*SST)*4u + kkB,
                      bf[2*p][0], bf[2*p][1], bf[2*p+1][0], bf[2*p+1][1]);
            #pragma unroll
            for (int mt = 0; mt < 2; mt++)
                #pragma unroll
                for (int nt = 0; nt < 8; nt++)
                    mma8(acc[mt][nt], af[mt], bf[nt]);
        }
    }
    __syncthreads();
}

// ---------------------------------------------------------------------------
// QKV projection (unchanged from R14)
// ---------------------------------------------------------------------------
__global__ void __launch_bounds__(256, 2) qkv_mma(
    const float* __restrict__ bq, const float* __restrict__ bk,
    const float* __restrict__ bv)
{
    const int m0  = blockIdx.x * BM;
    const int n0e = blockIdx.y * BN;
    const float* bias; int sel, nl0;
    if (n0e < 4096)      { bias = bq; sel = 0; nl0 = n0e; }
    else if (n0e < 5120) { bias = bk; sel = 1; nl0 = n0e - 4096; }
    else                 { bias = bv; sel = 2; nl0 = n0e - 5120; }

    float acc[2][8][4];
    gemm_mainloop(g_x + (size_t)m0*HID, g_wqkv + (size_t)n0e*HID, acc);

    const int lane = threadIdx.x & 31, w = threadIdx.x >> 5;
    const int wm = w & 3, wn = w >> 2;
    const int lq = lane >> 2, lr4 = lane & 3;

    #pragma unroll
    for (int mt = 0; mt < 2; mt++) {
        #pragma unroll
        for (int half = 0; half < 2; half++) {
            const int gm = m0 + wm*32 + mt*16 + lq + half*8;
            const int bb = gm >> 10, sq = gm & 1023;
            #pragma unroll
            for (int nt = 0; nt < 8; nt++) {
                const int nl = nl0 + wn*64 + nt*8 + lr4*2;
                const float2 bv2 = *reinterpret_cast<const float2*>(bias + nl);
                float2 v;
                v.x = acc[mt][nt][half*2 + 0] + bv2.x;
                v.y = acc[mt][nt][half*2 + 1] + bv2.y;
                const int h = nl >> 7, d = nl & 127;
                if (sel == 0) {
                    float* dst = &g_q[(((size_t)bb*NH + h)*QLEN + sq)*HD + d];
                    *reinterpret_cast<float2*>(dst) = v;
                } else if (sel == 1) {
                    float2 vr; vr.x = f2tf32(v.x); vr.y = f2tf32(v.y);
                    float* dst = &g_kc[(((size_t)bb*NKV + h)*KVLEN + PAST + sq)*HD + d];
                    *reinterpret_cast<float2*>(dst) = vr;
                } else {
                    float* dst = &g_vt[(((size_t)bb*NKV + h)*HD + d)*(size_t)KVLEN + PAST + sq];
                    dst[0]     = f2tf32(v.x);
                    dst[KVLEN] = f2tf32(v.y);
                }
            }
        }
    }
}

// ---------------------------------------------------------------------------
// Output projection (unchanged from R14)
// ---------------------------------------------------------------------------
__global__ void __launch_bounds__(256, 2) out_mma(
    const float* __restrict__ bo, float* __restrict__ out)
{
    const int m0 = blockIdx.x * BM;
    const int n0 = blockIdx.y * BN;

    float acc[2][8][4];
    gemm_mainloop(g_attn + (size_t)m0*HID, g_wo + (size_t)n0*HID, acc);

    const int lane = threadIdx.x & 31, w = threadIdx.x >> 5;
    const int wm = w & 3, wn = w >> 2;
    const int lq = lane >> 2, lr4 = lane & 3;

    #pragma unroll
    for (int mt = 0; mt < 2; mt++) {
        #pragma unroll
        for (int half = 0; half < 2; half++) {
            const int gm = m0 + wm*32 + mt*16 + lq + half*8;
            #pragma unroll
            for (int nt = 0; nt < 8; nt++) {
                const int gn = n0 + wn*64 + nt*8 + lr4*2;
                const float2 bv2 = *reinterpret_cast<const float2*>(bo + gn);
                float2 v;
                v.x = acc[mt][nt][half*2 + 0] + bv2.x;
                v.y = acc[mt][nt][half*2 + 1] + bv2.y;
                *reinterpret_cast<float2*>(out + (size_t)gm*HID + gn) = v;
            }
        }
    }
}

// ---------------------------------------------------------------------------
// Flash attention: 128 threads (4 warps x 16 q-rows), Q in registers,
// single-buffered K/V via cp.async, 2 CTAs/SM for cross-CTA overlap.
// ---------------------------------------------------------------------------
__global__ void __launch_bounds__(128, 2) attn_mma(
    const int* __restrict__ amask)
{
    extern __shared__ float sm[];
    float* Kb = sm;                    // [64][QST]   (also Q staging at start)
    float* Vb = Kb + 64*QST;           // [128][VST]
    float* Ps = Vb + 128*VST;          // [64][VST]

    const uint32_t smKb = smem_u32(Kb);
    const uint32_t smVb = smem_u32(Vb);
    const uint32_t smPs = smem_u32(Ps);

    const int b = blockIdx.z, h = blockIdx.y, q0 = blockIdx.x * AQ;
    const int hkv = h >> 2;
    const int tid = threadIdx.x;
    const int lane = tid & 31, w = tid >> 5;   // w = 0..3
    const int lq = lane >> 2, lr4 = lane & 3;
    const int qrow = w*16 + lq;

    const int a_r = (lane & 7) + ((lane >> 3) & 1) * 8;
    const int a_c = (lane >> 4) * 4;
    const uint32_t qstage = smKb + (uint32_t)((w*16 + a_r)*QST + a_c) * 4u;
    const uint32_t pfrag  = smPs + (uint32_t)((w*16 + a_r)*VST + a_c) * 4u;
    const int b_r = (lane & 7) + (lane >> 4) * 8;
    const int b_c = ((lane >> 3) & 1) * 4;
    const uint32_t kfrag = smKb + (uint32_t)(b_r*QST + b_c) * 4u;
    const uint32_t vfrag = smVb + (uint32_t)(b_r*VST + b_c) * 4u;

    const float* Kg = g_kc + ((size_t)b*NKV + hkv)*(size_t)KVLEN*HD;
    const float* Vg = g_vt + ((size_t)b*NKV + hkv)*(size_t)HD*KVLEN;
    const int*   mg = amask + (size_t)b * KVLEN;

    auto issue_K = [&](int kt){
        const float* src = Kg + (size_t)kt*64*HD;
        #pragma unroll
        for (int i = 0; i < 16; i++){
            const int c = tid + i*128;
            const int row = c >> 5, col = (c & 31) * 4;
            cpasync16(smKb + (uint32_t)(row*QST + col)*4u, src + (size_t)row*HD + col);
        }
    };
    auto issue_V = [&](int kt){
        const float* src = Vg + kt*64;
        #pragma unroll
        for (int i = 0; i < 16; i++){
            const int c = tid + i*128;
            const int row = c >> 4, col = (c & 15) * 4;
            cpasync16(smVb + (uint32_t)(row*VST + col)*4u, src + (size_t)row*KVLEN + col);
        }
    };

    // Stage Q through the K buffer (scaled + tf32-rounded), then ldsm to regs.
    {
        const float* Qg = g_q + (((size_t)b*NH + h)*QLEN + q0) * HD;
        #pragma unroll
        for (int i = 0; i < 16; i++) {
            const int c = tid + i*128;
            const int row = c >> 5, col = (c & 31) * 4;
            float4 q = *reinterpret_cast<const float4*>(Qg + (size_t)row*HD + col);
            float4 v;
            v.x = f2tf32(q.x * QSCALE); v.y = f2tf32(q.y * QSCALE);
            v.z = f2tf32(q.z * QSCALE); v.w = f2tf32(q.w * QSCALE);
            *reinterpret_cast<float4*>(Kb + row*QST + col) = v;
        }
    }
    __syncthreads();
    uint32_t qf[16][4];
    #pragma unroll
    for (int ks = 0; ks < 16; ks++)
        ldsm4(qstage + (uint32_t)ks*32u, qf[ks][0], qf[ks][1], qf[ks][2], qf[ks][3]);
    __syncthreads();      // all warps done reading Kb before K[0] overwrites it

    issue_K(0); CP_COMMIT();

    float oacc[16][4];
    #pragma unroll
    for (int d = 0; d < 16; d++)
        #pragma unroll
        for (int c = 0; c < 4; c++) oacc[d][c] = 0.f;
    float m0 = -3.0e38f, m1 = -3.0e38f, l0 = 0.f, l1 = 0.f;

    for (int kt = 0; kt < 32; kt++) {
        CP_WAIT0();                    // K[kt] arrived
        __syncthreads();               // PV[kt-1] done -> Vb reusable; Kb visible
        issue_V(kt); CP_COMMIT();

        // S = Q @ K^T
        float sacc[8][4];
        #pragma unroll
        for (int nt = 0; nt < 8; nt++)
            #pragma unroll
            for (int c = 0; c < 4; c++) sacc[nt][c] = 0.f;
        #pragma unroll
        for (int ks = 0; ks < 16; ks++) {
            const uint32_t kkB = (uint32_t)ks * 32u;
            uint32_t bf[8][2];
            #pragma unroll
            for (int p = 0; p < 4; p++)
                ldsm4(kfrag + (uint32_t)(p*16*QST)*4u + kkB,
                      bf[2*p][0], bf[2*p][1], bf[2*p+1][0], bf[2*p+1][1]);
            #pragma unroll
            for (int nt = 0; nt < 8; nt++)
                mma8(sacc[nt], qf[ks], bf[nt]);
        }
        __syncthreads();               // Kb free for next tile's K
        if (kt < 31) { issue_K(kt+1); CP_COMMIT(); }

        // mask bias (global, L1-resident) + online softmax
        float tmax0 = -3.0e38f, tmax1 = -3.0e38f;
        #pragma unroll
        for (int nt = 0; nt < 8; nt++) {
            const int ci = kt*64 + nt*8 + lr4*2;
            const float b0 = (mg[ci]   == 0) ? 0.f : NEGBIG;
            const float b1 = (mg[ci+1] == 0) ? 0.f : NEGBIG;
            sacc[nt][0] += b0; sacc[nt][1] += b1;
            sacc[nt][2] += b0; sacc[nt][3] += b1;
            tmax0 = fmaxf(tmax0, fmaxf(sacc[nt][0], sacc[nt][1]));
            tmax1 = fmaxf(tmax1, fmaxf(sacc[nt][2], sacc[nt][3]));
        }
        tmax0 = fmaxf(tmax0, __shfl_xor_sync(0xFFFFFFFFu, tmax0, 1));
        tmax0 = fmaxf(tmax0, __shfl_xor_sync(0xFFFFFFFFu, tmax0, 2));
        tmax1 = fmaxf(tmax1, __shfl_xor_sync(0xFFFFFFFFu, tmax1, 1));
        tmax1 = fmaxf(tmax1, __shfl_xor_sync(0xFFFFFFFFu, tmax1, 2));
        const float mn0 = fmaxf(m0, tmax0), mn1 = fmaxf(m1, tmax1);
        const float sc0 = __expf(m0 - mn0), sc1 = __expf(m1 - mn1);
        float sum0 = 0.f, sum1 = 0.f;
        #pragma unroll
        for (int nt = 0; nt < 8; nt++) {
            const float p00 = __expf(sacc[nt][0] - mn0);
            const float p01 = __expf(sacc[nt][1] - mn0);
            const float p10 = __expf(sacc[nt][2] - mn1);
            const float p11 = __expf(sacc[nt][3] - mn1);
            sum0 += p00 + p01; sum1 += p10 + p11;
            float2 s0; s0.x = f2tf32(p00); s0.y = f2tf32(p01);
            *reinterpret_cast<float2*>(Ps + qrow*VST + nt*8 + lr4*2) = s0;
            float2 s1; s1.x = f2tf32(p10); s1.y = f2tf32(p11);
            *reinterpret_cast<float2*>(Ps + (qrow+8)*VST + nt*8 + lr4*2) = s1;
        }
        sum0 += __shfl_xor_sync(0xFFFFFFFFu, sum0, 1);
        sum0 += __shfl_xor_sync(0xFFFFFFFFu, sum0, 2);
        sum1 += __shfl_xor_sync(0xFFFFFFFFu, sum1, 1);
        sum1 += __shfl_xor_sync(0xFFFFFFFFu, sum1, 2);
        l0 = l0*sc0 + sum0; l1 = l1*sc1 + sum1;
        m0 = mn0; m1 = mn1;
        #pragma unroll
        for (int d = 0; d < 16; d++) {
            oacc[d][0] *= sc0; oacc[d][1] *= sc0;
            oacc[d][2] *= sc1; oacc[d][3] *= sc1;
        }
        __syncwarp();                  // P stores visible to own warp's ldmatrix

        if (kt < 31) { CP_WAIT1(); } else { CP_WAIT0(); }   // V[kt] done, K[kt+1] flying
        __syncthreads();

        // O += P @ V
        #pragma unroll
        for (int ks = 0; ks < 8; ks++) {
            const uint32_t kkB = (uint32_t)ks * 32u;
            uint32_t af[4];
            ldsm4(pfrag + kkB, af[0], af[1], af[2], af[3]);
            #pragma unroll
            for (int p = 0; p < 8; p++) {
                uint32_t bf0, bf1, bf2, bf3;
                ldsm4(vfrag + (uint32_t)(p*16*VST)*4u + kkB, bf0, bf1, bf2, bf3);
                uint32_t bfa[2] = { bf0, bf1 };
                uint32_t bfb[2] = { bf2, bf3 };
                mma8(oacc[2*p],     af, bfa);
                mma8(oacc[2*p + 1], af, bfb);
            }
        }
    }

    // normalize + write [B*S, H*D], tf32-rounded (consumed verbatim by out_mma)
    const float inv0 = 1.f / l0, inv1 = 1.f / l1;
    float* orow0 = g_attn + ((size_t)(b*QLEN + q0 + w*16 + lq))*HID + h*HD;
    float* orow1 = orow0 + (size_t)8*HID;
    #pragma unroll
    for (int d = 0; d < 16; d++) {
        float2 v0; v0.x = f2tf32(oacc[d][0]*inv0); v0.y = f2tf32(oacc[d][1]*inv0);
        *reinterpret_cast<float2*>(orow0 + d*8 + lr4*2) = v0;
        float2 v1; v1.x = f2tf32(oacc[d][2]*inv1); v1.y = f2tf32(oacc[d][3]*inv1);
        *reinterpret_cast<float2*>(orow1 + d*8 + lr4*2) = v1;
    }
}

// ---------------------------------------------------------------------------
extern "C" void kernel_launch(void* const* d_in, const int* in_sizes, int n_in,
                              void* d_out, int out_size)
{
    const float* hs = (const float*)d_in[0];
    const float* pk = (const float*)d_in[1];
    const float* pv = (const float*)d_in[2];
    const int*   mk = (const int*)  d_in[3];
    const float* Wq = (const float*)d_in[4];
    const float* bq = (const float*)d_in[5];
    const float* Wk = (const float*)d_in[6];
    const float* bk = (const float*)d_in[7];
    const float* Wv = (const float*)d_in[8];
    const float* bv = (const float*)d_in[9];
    const float* Wo = (const float*)d_in[10];
    const float* bo = (const float*)d_in[11];
    float* out = (float*)d_out;

    cudaFuncSetAttribute(qkv_mma, cudaFuncAttributeMaxDynamicSharedMemorySize, GSMEM);
    cudaFuncSetAttribute(out_mma, cudaFuncAttributeMaxDynamicSharedMemorySize, GSMEM);
    cudaFuncSetAttribute(attn_mma, cudaFuncAttributeMaxDynamicSharedMemorySize, ATTN_SM_BYTES);

    cvt_all<<<2048, 256>>>(hs, Wq, Wk, Wv, Wo, pk);

    dim3 gv(NB*NKV, PAST/32, HD/32);      // 32 x 32 x 4
    vtrans<<<gv, 256>>>(pv);

    dim3 g1(MROWS/BM, 6144/BN);           // 32 x 48
    qkv_mma<<<g1, 256, GSMEM>>>(bq, bk, bv);

    dim3 g2(QLEN/AQ, NH, NB);             // 16 x 32 x 4
    attn_mma<<<g2, 128, ATTN_SM_BYTES>>>(mk);

    dim3 g3(MROWS/BM, HID/BN);            // 32 x 32
    out_mma<<<g3, 256, GSMEM>>>(bo, out);
}

// round 16
// speedup vs baseline: 1.3653x; 1.0339x over previous
#include <cuda_runtime.h>
#include <cstdint>
#include <math.h>

// Problem constants
#define HID   4096
#define NB    4
#define QLEN  1024
#define NH    32
#define NKV   8
#define HD    128
#define PAST  1024
#define KVLEN 2048
#define MROWS (NB*QLEN)   // 4096
#define QSCALE 0.08838834764831845f
#define NEGBIG (-1.0e9f)

// GEMM tiling: 128x128 CTA tile, BK=16, 4 warps (2x2) of 64x64, cp.async 4-stage
#define BM 128
#define BN 128
#define BK 16
#define NKITER (HID/BK)     // 256
#define SST 20
#define NSTAGE 4
#define STAGEF (256*SST)
#define STAGEB (STAGEF*4)   // 20480 bytes
#define GSMEM (NSTAGE*STAGEB)   // 81920 bytes

// Attention tiling (unchanged from R15-passing kernel)
#define AQ  64
#define AKV 64
#define QST 132
#define VST 68
#define ATTN_SM_BYTES ((64*QST + 128*VST + 64*VST) * 4)   // 86016

// Scratch (device globals — allocation-free)
__device__ float g_q   [(size_t)NB*NH *QLEN*HD];
__device__ float g_kc  [(size_t)NB*NKV*KVLEN*HD];
__device__ float g_vt  [(size_t)NB*NKV*HD*KVLEN];
__device__ float g_attn[(size_t)MROWS*HID];
__device__ float g_x   [(size_t)MROWS*HID];
__device__ float g_wqkv[(size_t)6144*HID];
__device__ float g_wo  [(size_t)HID*HID];

// ---------------------------------------------------------------------------
__device__ __forceinline__ float f2tf32(float x){
    uint32_t r; asm("cvt.rna.tf32.f32 %0, %1;" : "=r"(r) : "f"(x));
    return __uint_as_float(r);
}
__device__ __forceinline__ uint32_t smem_u32(const void* p){
    uint32_t a;
    asm("{ .reg .u64 t; cvta.to.shared.u64 t, %1; cvt.u32.u64 %0, t; }" : "=r"(a) : "l"(p));
    return a;
}
__device__ __forceinline__ void mma8(float* d, const uint32_t* a, const uint32_t* b){
    asm volatile(
        "mma.sync.aligned.m16n8k8.row.col.f32.tf32.tf32.f32 "
        "{%0,%1,%2,%3}, {%4,%5,%6,%7}, {%8,%9}, {%0,%1,%2,%3};"
        : "+f"(d[0]), "+f"(d[1]), "+f"(d[2]), "+f"(d[3])
        : "r"(a[0]), "r"(a[1]), "r"(a[2]), "r"(a[3]), "r"(b[0]), "r"(b[1]));
}
__device__ __forceinline__ void ldsm4(uint32_t addr, uint32_t& r0, uint32_t& r1,
                                      uint32_t& r2, uint32_t& r3){
    asm volatile("ldmatrix.sync.aligned.m8n8.x4.shared.b16 {%0,%1,%2,%3}, [%4];"
        : "=r"(r0), "=r"(r1), "=r"(r2), "=r"(r3) : "r"(addr));
}
__device__ __forceinline__ void cpasync16(uint32_t dst, const void* src){
    asm volatile("cp.async.ca.shared.global [%0], [%1], 16;" :: "r"(dst), "l"(src));
}
#define CP_COMMIT() asm volatile("cp.async.commit_group;" ::: "memory")
#define CP_WAIT0()  asm volatile("cp.async.wait_group 0;" ::: "memory")
#define CP_WAIT1()  asm volatile("cp.async.wait_group 1;" ::: "memory")
#define CP_WAIT2()  asm volatile("cp.async.wait_group 2;" ::: "memory")

// ---------------------------------------------------------------------------
// One-time operand conversion (unchanged)
// ---------------------------------------------------------------------------
__global__ void cvt_all(const float* __restrict__ X,
                        const float* __restrict__ Wq, const float* __restrict__ Wk,
                        const float* __restrict__ Wv, const float* __restrict__ Wo,
                        const float* __restrict__ pastK)
{
    const size_t nX  = (size_t)MROWS*HID/4;
    const size_t nWq = (size_t)HID*HID/4;
    const size_t nWk = (size_t)(NKV*HD)*HID/4;
    const size_t nKp = (size_t)NB*NKV*PAST*HD/4;
    const size_t nTot = nX + nWq + 2*nWk + nKp + nWq;
    for (size_t i = blockIdx.x*(size_t)blockDim.x + threadIdx.x; i < nTot;
         i += (size_t)gridDim.x*blockDim.x) {
        size_t j = i; const float4* s; float4* dp;
        if (j < nX)                { s = (const float4*)X + j;  dp = (float4*)g_x + j; }
        else if ((j -= nX) < nWq)  { s = (const float4*)Wq + j; dp = (float4*)g_wqkv + j; }
        else if ((j -= nWq) < nWk) { s = (const float4*)Wk + j; dp = (float4*)(g_wqkv + (size_t)4096*HID) + j; }
        else if ((j -= nWk) < nWk) { s = (const float4*)Wv + j; dp = (float4*)(g_wqkv + (size_t)5120*HID) + j; }
        else if ((j -= nWk) < nKp) {
            s = (const float4*)pastK + j;
            const size_t per = (size_t)PAST*HD/4;
            const size_t bh = j / per, rem = j - bh*per;
            dp = (float4*)g_kc + bh*((size_t)KVLEN*HD/4) + rem;
        }
        else                       { j -= nKp; s = (const float4*)Wo + j; dp = (float4*)g_wo + j; }
        float4 v = *s;
        v.x = f2tf32(v.x); v.y = f2tf32(v.y); v.z = f2tf32(v.z); v.w = f2tf32(v.w);
        *dp = v;
    }
}

// ---------------------------------------------------------------------------
// Past-V transpose (unchanged)
// ---------------------------------------------------------------------------
__global__ void vtrans(const float* __restrict__ pastV)
{
    __shared__ float t[32][33];
    const int bh  = blockIdx.x;
    const int kv0 = blockIdx.y * 32;
    const int d0  = blockIdx.z * 32;
    const int tx = threadIdx.x & 31, ty = threadIdx.x >> 5;
    const float* src = pastV + ((size_t)bh*PAST + kv0)*HD + d0;
    #pragma unroll
    for (int i = 0; i < 4; i++)
        t[ty + i*8][tx] = f2tf32(src[(size_t)(ty + i*8)*HD + tx]);
    __syncthreads();
    float* dst = g_vt + ((size_t)bh*HD + d0)*KVLEN + kv0;
    #pragma unroll
    for (int i = 0; i < 4; i++)
        dst[(size_t)(ty + i*8)*KVLEN + tx] = t[tx][ty + i*8];
}

// ---------------------------------------------------------------------------
// GEMM mainloop: 128 threads, 4 warps (2x2), warp tile 64x64.
// ---------------------------------------------------------------------------
__device__ __forceinline__ void gemm_mainloop(
    const float* __restrict__ Ag, const float* __restrict__ Bg,
    float (&acc)[4][8][4])
{
    extern __shared__ float sm[];
    const uint32_t smbase = smem_u32(sm);

    const int tid  = threadIdx.x;
    const int lane = tid & 31;
    const int w    = tid >> 5;       // 0..3
    const int wm   = w & 1;          // M tile of 64
    const int wn   = w >> 1;         // N tile of 64

    #pragma unroll
    for (int mt = 0; mt < 4; mt++)
        #pragma unroll
        for (int nt = 0; nt < 8; nt++)
            #pragma unroll
            for (int c = 0; c < 4; c++) acc[mt][nt][c] = 0.f;

    const int arow = wm*64 + (lane & 7) + ((lane >> 3) & 1) * 8;
    const int acol = (lane >> 4) * 4;
    const uint32_t aoff = (uint32_t)(arow*SST + acol) * 4u;
    const int brow = wn*64 + (lane & 7) + (lane >> 4) * 8;
    const int bcol = ((lane >> 3) & 1) * 4;
    const uint32_t boff = (uint32_t)((128 + brow)*SST + bcol) * 4u;

    // staging: 128 threads, 8 cpasync16/thread/stage (A 512 f4 + B 512 f4)
    const int r0 = tid >> 2, c0 = (tid & 3) * 4;   // rows 0..31

    auto issue_stage = [&](int s, int k0){
        const uint32_t base = smbase + (uint32_t)s*STAGEB;
        const uint32_t bb   = base + (uint32_t)(128*SST)*4u;
        #pragma unroll
        for (int j = 0; j < 4; j++) {
            const int row = r0 + j*32;
            cpasync16(base + (uint32_t)(row*SST + c0)*4u, Ag + (size_t)row*HID + k0 + c0);
            cpasync16(bb   + (uint32_t)(row*SST + c0)*4u, Bg + (size_t)row*HID + k0 + c0);
        }
    };

    #pragma unroll
    for (int s = 0; s < NSTAGE-1; s++) { issue_stage(s, s*BK); CP_COMMIT(); }

    for (int kt = 0; kt < NKITER; kt++) {
        CP_WAIT2();
        __syncthreads();
        if (kt + NSTAGE-1 < NKITER) issue_stage((kt + NSTAGE-1) & 3, (kt + NSTAGE-1) * BK);
        CP_COMMIT();

        const uint32_t Sbase = smbase + (uint32_t)(kt & 3)*STAGEB;
        const uint32_t Aaddr = Sbase + aoff;
        const uint32_t Baddr = Sbase + boff;
        #pragma unroll
        for (int ks = 0; ks < 2; ks++) {
            const uint32_t kkB = (uint32_t)(ks * 8) * 4u;
            uint32_t af[4][4], bf[8][2];
            #pragma unroll
            for (int mt = 0; mt < 4; mt++)
                ldsm4(Aaddr + (uint32_t)(mt*16*SST)*4u + kkB,
                      af[mt][0], af[mt][1], af[mt][2], af[mt][3]);
            #pragma unroll
            for (int p = 0; p < 4; p++)
                ldsm4(Baddr + (uint32_t)(p*16*SST)*4u + kkB,
                      bf[2*p][0], bf[2*p][1], bf[2*p+1][0], bf[2*p+1][1]);
            #pragma unroll
            for (int mt = 0; mt < 4; mt++)
                #pragma unroll
                for (int nt = 0; nt < 8; nt++)
                    mma8(acc[mt][nt], af[mt], bf[nt]);
        }
    }
    __syncthreads();
}

// ---------------------------------------------------------------------------
// QKV projection: 128 threads, warp tile 64x64
// ---------------------------------------------------------------------------
__global__ void __launch_bounds__(128, 2) qkv_mma(
    const float* __restrict__ bq, const float* __restrict__ bk,
    const float* __restrict__ bv)
{
    const int m0  = blockIdx.x * BM;
    const int n0e = blockIdx.y * BN;
    const float* bias; int sel, nl0;
    if (n0e < 4096)      { bias = bq; sel = 0; nl0 = n0e; }
    else if (n0e < 5120) { bias = bk; sel = 1; nl0 = n0e - 4096; }
    else                 { bias = bv; sel = 2; nl0 = n0e - 5120; }

    float acc[4][8][4];
    gemm_mainloop(g_x + (size_t)m0*HID, g_wqkv + (size_t)n0e*HID, acc);

    const int lane = threadIdx.x & 31, w = threadIdx.x >> 5;
    const int wm = w & 1, wn = w >> 1;
    const int lq = lane >> 2, lr4 = lane & 3;

    #pragma unroll
    for (int mt = 0; mt < 4; mt++) {
        #pragma unroll
        for (int half = 0; half < 2; half++) {
            const int gm = m0 + wm*64 + mt*16 + lq + half*8;
            const int bb = gm >> 10, sq = gm & 1023;
            #pragma unroll
            for (int nt = 0; nt < 8; nt++) {
                const int nl = nl0 + wn*64 + nt*8 + lr4*2;
                const float2 bv2 = *reinterpret_cast<const float2*>(bias + nl);
                float2 v;
                v.x = acc[mt][nt][half*2 + 0] + bv2.x;
                v.y = acc[mt][nt][half*2 + 1] + bv2.y;
                const int h = nl >> 7, d = nl & 127;
                if (sel == 0) {
                    float* dst = &g_q[(((size_t)bb*NH + h)*QLEN + sq)*HD + d];
                    *reinterpret_cast<float2*>(dst) = v;
                } else if (sel == 1) {
                    float2 vr; vr.x = f2tf32(v.x); vr.y = f2tf32(v.y);
                    float* dst = &g_kc[(((size_t)bb*NKV + h)*KVLEN + PAST + sq)*HD + d];
                    *reinterpret_cast<float2*>(dst) = vr;
                } else {
                    float* dst = &g_vt[(((size_t)bb*NKV + h)*HD + d)*(size_t)KVLEN + PAST + sq];
                    dst[0]     = f2tf32(v.x);
                    dst[KVLEN] = f2tf32(v.y);
                }
            }
        }
    }
}

// ---------------------------------------------------------------------------
// Output projection: 128 threads, warp tile 64x64
// ---------------------------------------------------------------------------
__global__ void __launch_bounds__(128, 2) out_mma(
    const float* __restrict__ bo, float* __restrict__ out)
{
    const int m0 = blockIdx.x * BM;
    const int n0 = blockIdx.y * BN;

    float acc[4][8][4];
    gemm_mainloop(g_attn + (size_t)m0*HID, g_wo + (size_t)n0*HID, acc);

    const int lane = threadIdx.x & 31, w = threadIdx.x >> 5;
    const int wm = w & 1, wn = w >> 1;
    const int lq = lane >> 2, lr4 = lane & 3;

    #pragma unroll
    for (int mt = 0; mt < 4; mt++) {
        #pragma unroll
        for (int half = 0; half < 2; half++) {
            const int gm = m0 + wm*64 + mt*16 + lq + half*8;
            #pragma unroll
            for (int nt = 0; nt < 8; nt++) {
                const int gn = n0 + wn*64 + nt*8 + lr4*2;
                const float2 bv2 = *reinterpret_cast<const float2*>(bo + gn);
                float2 v;
                v.x = acc[mt][nt][half*2 + 0] + bv2.x;
                v.y = acc[mt][nt][half*2 + 1] + bv2.y;
                *reinterpret_cast<float2*>(out + (size_t)gm*HID + gn) = v;
            }
        }
    }
}

// ---------------------------------------------------------------------------
// Flash attention (unchanged from R15-passing kernel)
// ---------------------------------------------------------------------------
__global__ void __launch_bounds__(128, 2) attn_mma(
    const int* __restrict__ amask)
{
    extern __shared__ float sm[];
    float* Kb = sm;                    // [64][QST]   (also Q staging at start)
    float* Vb = Kb + 64*QST;           // [128][VST]
    float* Ps = Vb + 128*VST;          // [64][VST]

    const uint32_t smKb = smem_u32(Kb);
    const uint32_t smVb = smem_u32(Vb);
    const uint32_t smPs = smem_u32(Ps);

    const int b = blockIdx.z, h = blockIdx.y, q0 = blockIdx.x * AQ;
    const int hkv = h >> 2;
    const int tid = threadIdx.x;
    const int lane = tid & 31, w = tid >> 5;
    const int lq = lane >> 2, lr4 = lane & 3;
    const int qrow = w*16 + lq;

    const int a_r = (lane & 7) + ((lane >> 3) & 1) * 8;
    const int a_c = (lane >> 4) * 4;
    const uint32_t qstage = smKb + (uint32_t)((w*16 + a_r)*QST + a_c) * 4u;
    const uint32_t pfrag  = smPs + (uint32_t)((w*16 + a_r)*VST + a_c) * 4u;
    const int b_r = (lane & 7) + (lane >> 4) * 8;
    const int b_c = ((lane >> 3) & 1) * 4;
    const uint32_t kfrag = smKb + (uint32_t)(b_r*QST + b_c) * 4u;
    const uint32_t vfrag = smVb + (uint32_t)(b_r*VST + b_c) * 4u;

    const float* Kg = g_kc + ((size_t)b*NKV + hkv)*(size_t)KVLEN*HD;
    const float* Vg = g_vt + ((size_t)b*NKV + hkv)*(size_t)HD*KVLEN;
    const int*   mg = amask + (size_t)b * KVLEN;

    auto issue_K = [&](int kt){
        const float* src = Kg + (size_t)kt*64*HD;
        #pragma unroll
        for (int i = 0; i < 16; i++){
            const int c = tid + i*128;
            const int row = c >> 5, col = (c & 31) * 4;
            cpasync16(smKb + (uint32_t)(row*QST + col)*4u, src + (size_t)row*HD + col);
        }
    };
    auto issue_V = [&](int kt){
        const float* src = Vg + kt*64;
        #pragma unroll
        for (int i = 0; i < 16; i++){
            const int c = tid + i*128;
            const int row = c >> 4, col = (c & 15) * 4;
            cpasync16(smVb + (uint32_t)(row*VST + col)*4u, src + (size_t)row*KVLEN + col);
        }
    };

    {
        const float* Qg = g_q + (((size_t)b*NH + h)*QLEN + q0) * HD;
        #pragma unroll
        for (int i = 0; i < 16; i++) {
            const int c = tid + i*128;
            const int row = c >> 5, col = (c & 31) * 4;
            float4 q = *reinterpret_cast<const float4*>(Qg + (size_t)row*HD + col);
            float4 v;
            v.x = f2tf32(q.x * QSCALE); v.y = f2tf32(q.y * QSCALE);
            v.z = f2tf32(q.z * QSCALE); v.w = f2tf32(q.w * QSCALE);
            *reinterpret_cast<float4*>(Kb + row*QST + col) = v;
        }
    }
    __syncthreads();
    uint32_t qf[16][4];
    #pragma unroll
    for (int ks = 0; ks < 16; ks++)
        ldsm4(qstage + (uint32_t)ks*32u, qf[ks][0], qf[ks][1], qf[ks][2], qf[ks][3]);
    __syncthreads();

    issue_K(0); CP_COMMIT();

    float oacc[16][4];
    #pragma unroll
    for (int d = 0; d < 16; d++)
        #pragma unroll
        for (int c = 0; c < 4; c++) oacc[d][c] = 0.f;
    float m0 = -3.0e38f, m1 = -3.0e38f, l0 = 0.f, l1 = 0.f;

    for (int kt = 0; kt < 32; kt++) {
        CP_WAIT0();
        __syncthreads();
        issue_V(kt); CP_COMMIT();

        float sacc[8][4];
        #pragma unroll
        for (int nt = 0; nt < 8; nt++)
            #pragma unroll
            for (int c = 0; c < 4; c++) sacc[nt][c] = 0.f;
        #pragma unroll
        for (int ks = 0; ks < 16; ks++) {
            const uint32_t kkB = (uint32_t)ks * 32u;
            uint32_t bf[8][2];
            #pragma unroll
            for (int p = 0; p < 4; p++)
                ldsm4(kfrag + (uint32_t)(p*16*QST)*4u + kkB,
                      bf[2*p][0], bf[2*p][1], bf[2*p+1][0], bf[2*p+1][1]);
            #pragma unroll
            for (int nt = 0; nt < 8; nt++)
                mma8(sacc[nt], qf[ks], bf[nt]);
        }
        __syncthreads();
        if (kt < 31) { issue_K(kt+1); CP_COMMIT(); }

        float tmax0 = -3.0e38f, tmax1 = -3.0e38f;
        #pragma unroll
        for (int nt = 0; nt < 8; nt++) {
            const int ci = kt*64 + nt*8 + lr4*2;
            const float b0 = (mg[ci]   == 0) ? 0.f : NEGBIG;
            const float b1 = (mg[ci+1] == 0) ? 0.f : NEGBIG;
            sacc[nt][0] += b0; sacc[nt][1] += b1;
            sacc[nt][2] += b0; sacc[nt][3] += b1;
            tmax0 = fmaxf(tmax0, fmaxf(sacc[nt][0], sacc[nt][1]));
            tmax1 = fmaxf(tmax1, fmaxf(sacc[nt][2], sacc[nt][3]));
        }
        tmax0 = fmaxf(tmax0, __shfl_xor_sync(0xFFFFFFFFu, tmax0, 1));
        tmax0 = fmaxf(tmax0, __shfl_xor_sync(0xFFFFFFFFu, tmax0, 2));
        tmax1 = fmaxf(tmax1, __shfl_xor_sync(0xFFFFFFFFu, tmax1, 1));
        tmax1 = fmaxf(tmax1, __shfl_xor_sync(0xFFFFFFFFu, tmax1, 2));
        const float mn0 = fmaxf(m0, tmax0), mn1 = fmaxf(m1, tmax1);
        const float sc0 = __expf(m0 - mn0), sc1 = __expf(m1 - mn1);
        float sum0 = 0.f, sum1 = 0.f;
        #pragma unroll
        for (int nt = 0; nt < 8; nt++) {
            const float p00 = __expf(sacc[nt][0] - mn0);
            const float p01 = __expf(sacc[nt][1] - mn0);
            const float p10 = __expf(sacc[nt][2] - mn1);
            const float p11 = __expf(sacc[nt][3] - mn1);
            sum0 += p00 + p01; sum1 += p10 + p11;
            float2 s0; s0.x = f2tf32(p00); s0.y = f2tf32(p01);
            *reinterpret_cast<float2*>(Ps + qrow*VST + nt*8 + lr4*2) = s0;
            float2 s1; s1.x = f2tf32(p10); s1.y = f2tf32(p11);
            *reinterpret_cast<float2*>(Ps + (qrow+8)*VST + nt*8 + lr4*2) = s1;
        }
        sum0 += __shfl_xor_sync(0xFFFFFFFFu, sum0, 1);
        sum0 += __shfl_xor_sync(0xFFFFFFFFu, sum0, 2);
        sum1 += __shfl_xor_sync(0xFFFFFFFFu, sum1, 1);
        sum1 += __shfl_xor_sync(0xFFFFFFFFu, sum1, 2);
        l0 = l0*sc0 + sum0; l1 = l1*sc1 + sum1;
        m0 = mn0; m1 = mn1;
        #pragma unroll
        for (int d = 0; d < 16; d++) {
            oacc[d][0] *= sc0; oacc[d][1] *= sc0;
            oacc[d][2] *= sc1; oacc[d][3] *= sc1;
        }
        __syncwarp();

        if (kt < 31) { CP_WAIT1(); } else { CP_WAIT0(); }
        __syncthreads();

        #pragma unroll
        for (int ks = 0; ks < 8; ks++) {
            const uint32_t kkB = (uint32_t)ks * 32u;
            uint32_t af[4];
            ldsm4(pfrag + kkB, af[0], af[1], af[2], af[3]);
            #pragma unroll
            for (int p = 0; p < 8; p++) {
                uint32_t bf0, bf1, bf2, bf3;
                ldsm4(vfrag + (uint32_t)(p*16*VST)*4u + kkB, bf0, bf1, bf2, bf3);
                uint32_t bfa[2] = { bf0, bf1 };
                uint32_t bfb[2] = { bf2, bf3 };
                mma8(oacc[2*p],     af, bfa);
                mma8(oacc[2*p + 1], af, bfb);
            }
        }
    }

    const float inv0 = 1.f / l0, inv1 = 1.f / l1;
    float* orow0 = g_attn + ((size_t)(b*QLEN + q0 + w*16 + lq))*HID + h*HD;
    float* orow1 = orow0 + (size_t)8*HID;
    #pragma unroll
    for (int d = 0; d < 16; d++) {
        float2 v0; v0.x = f2tf32(oacc[d][0]*inv0); v0.y = f2tf32(oacc[d][1]*inv0);
        *reinterpret_cast<float2*>(orow0 + d*8 + lr4*2) = v0;
        float2 v1; v1.x = f2tf32(oacc[d][2]*inv1); v1.y = f2tf32(oacc[d][3]*inv1);
        *reinterpret_cast<float2*>(orow1 + d*8 + lr4*2) = v1;
    }
}

// ---------------------------------------------------------------------------
extern "C" void kernel_launch(void* const* d_in, const int* in_sizes, int n_in,
                              void* d_out, int out_size)
{
    const float* hs = (const float*)d_in[0];
    const float* pk = (const float*)d_in[1];
    const float* pv = (const float*)d_in[2];
    const int*   mk = (const int*)  d_in[3];
    const float* Wq = (const float*)d_in[4];
    const float* bq = (const float*)d_in[5];
    const float* Wk = (const float*)d_in[6];
    const float* bk = (const float*)d_in[7];
    const float* Wv = (const float*)d_in[8];
    const float* bv = (const float*)d_in[9];
    const float* Wo = (const float*)d_in[10];
    const float* bo = (const float*)d_in[11];
    float* out = (float*)d_out;

    cudaFuncSetAttribute(qkv_mma, cudaFuncAttributeMaxDynamicSharedMemorySize, GSMEM);
    cudaFuncSetAttribute(out_mma, cudaFuncAttributeMaxDynamicSharedMemorySize, GSMEM);
    cudaFuncSetAttribute(attn_mma, cudaFuncAttributeMaxDynamicSharedMemorySize, ATTN_SM_BYTES);

    cvt_all<<<2048, 256>>>(hs, Wq, Wk, Wv, Wo, pk);

    dim3 gv(NB*NKV, PAST/32, HD/32);
    vtrans<<<gv, 256>>>(pv);

    dim3 g1(MROWS/BM, 6144/BN);           // 32 x 48
    qkv_mma<<<g1, 128, GSMEM>>>(bq, bk, bv);

    dim3 g2(QLEN/AQ, NH, NB);             // 16 x 32 x 4
    attn_mma<<<g2, 128, ATTN_SM_BYTES>>>(mk);

    dim3 g3(MROWS/BM, HID/BN);            // 32 x 32
    out_mma<<<g3, 128, GSMEM>>>(bo, out);
}

// round 17
// speedup vs baseline: 2.5771x; 1.8876x over previous
#include <cuda_runtime.h>
#include <cuda_fp16.h>
#include <cstdint>
#include <math.h>

// Problem constants
#define HID   4096
#define NB    4
#define QLEN  1024
#define NH    32
#define NKV   8
#define HD    128
#define PAST  1024
#define KVLEN 2048
#define MROWS (NB*QLEN)   // 4096
#define QSCALE 0.08838834764831845f
#define NEGBIG (-1.0e9f)

// GEMM tiling: 128x128 CTA, BK=32 halves, 4 warps (2x2) 64x64, cp.async 4-stage
#define BM 128
#define BN 128
#define BKH 32              // K halves per iter
#define NKITER (HID/BKH)    // 128
#define SSTH 40             // smem row stride in halves (80 B; conflict-free)
#define SSTB 80
#define NSTAGE 4
#define STAGEB (256*SSTB)   // 20480 bytes
#define GSMEM (NSTAGE*STAGEB)   // 81920 bytes

// Attention tiling: 128 threads, 64 q-rows/CTA, 2 CTAs/SM (halved smem)
#define AQ  64
#define KSTH 136            // K/Q row stride halves (272 B; 68 words == 4 mod 32)
#define KSTB 272
#define VSTH 72             // V/P row stride halves (144 B; 36 words == 4 mod 32)
#define VSTB 144
#define ATTN_SM_BYTES (64*KSTB + 128*VSTB + 64*VSTB)   // 45056

// Scratch (device globals — allocation-free), all fp16 operands
__device__ __half g_qh  [(size_t)NB*NH *QLEN*HD];    // [B,H,S,D] scaled+rounded
__device__ __half g_kc  [(size_t)NB*NKV*KVLEN*HD];   // [B,Hkv,KV,D]
__device__ __half g_vt  [(size_t)NB*NKV*HD*KVLEN];   // [B,Hkv,D,KV] transposed
__device__ __half g_attn[(size_t)MROWS*HID];         // attn out (half)
__device__ __half g_x   [(size_t)MROWS*HID];
__device__ __half g_wqkv[(size_t)6144*HID];
__device__ __half g_wo  [(size_t)HID*HID];

// ---------------------------------------------------------------------------
__device__ __forceinline__ uint32_t smem_u32(const void* p){
    uint32_t a;
    asm("{ .reg .u64 t; cvta.to.shared.u64 t, %1; cvt.u32.u64 %0, t; }" : "=r"(a) : "l"(p));
    return a;
}
__device__ __forceinline__ void mma16(float* d, const uint32_t* a, const uint32_t* b){
    asm volatile(
        "mma.sync.aligned.m16n8k16.row.col.f32.f16.f16.f32 "
        "{%0,%1,%2,%3}, {%4,%5,%6,%7}, {%8,%9}, {%0,%1,%2,%3};"
        : "+f"(d[0]), "+f"(d[1]), "+f"(d[2]), "+f"(d[3])
        : "r"(a[0]), "r"(a[1]), "r"(a[2]), "r"(a[3]), "r"(b[0]), "r"(b[1]));
}
__device__ __forceinline__ void ldsm4(uint32_t addr, uint32_t& r0, uint32_t& r1,
                                      uint32_t& r2, uint32_t& r3){
    asm volatile("ldmatrix.sync.aligned.m8n8.x4.shared.b16 {%0,%1,%2,%3}, [%4];"
        : "=r"(r0), "=r"(r1), "=r"(r2), "=r"(r3) : "r"(addr));
}
__device__ __forceinline__ void cpasync16(uint32_t dst, const void* src){
    asm volatile("cp.async.ca.shared.global [%0], [%1], 16;" :: "r"(dst), "l"(src));
}
#define CP_COMMIT() asm volatile("cp.async.commit_group;" ::: "memory")
#define CP_WAIT0()  asm volatile("cp.async.wait_group 0;" ::: "memory")
#define CP_WAIT1()  asm volatile("cp.async.wait_group 1;" ::: "memory")
#define CP_WAIT2()  asm volatile("cp.async.wait_group 2;" ::: "memory")

// ---------------------------------------------------------------------------
// One-time operand conversion: fp32 -> fp16(RN). Also copies past K into the
// combined KV buffer (rows [0, PAST)). float4 -> 8-byte half4 per index.
// ---------------------------------------------------------------------------
__global__ void cvt_all(const float* __restrict__ X,
                        const float* __restrict__ Wq, const float* __restrict__ Wk,
                        const float* __restrict__ Wv, const float* __restrict__ Wo,
                        const float* __restrict__ pastK)
{
    const size_t nX  = (size_t)MROWS*HID/4;
    const size_t nWq = (size_t)HID*HID/4;
    const size_t nWk = (size_t)(NKV*HD)*HID/4;
    const size_t nKp = (size_t)NB*NKV*PAST*HD/4;
    const size_t nTot = nX + nWq + 2*nWk + nKp + nWq;
    for (size_t i = blockIdx.x*(size_t)blockDim.x + threadIdx.x; i < nTot;
         i += (size_t)gridDim.x*blockDim.x) {
        size_t j = i; const float4* s; uint2* dp;
        if (j < nX)                { s = (const float4*)X + j;  dp = (uint2*)g_x + j; }
        else if ((j -= nX) < nWq)  { s = (const float4*)Wq + j; dp = (uint2*)g_wqkv + j; }
        else if ((j -= nWq) < nWk) { s = (const float4*)Wk + j; dp = (uint2*)(g_wqkv + (size_t)4096*HID) + j; }
        else if ((j -= nWk) < nWk) { s = (const float4*)Wv + j; dp = (uint2*)(g_wqkv + (size_t)5120*HID) + j; }
        else if ((j -= nWk) < nKp) {
            s = (const float4*)pastK + j;
            const size_t per = (size_t)PAST*HD/4;
            const size_t bh = j / per, rem = j - bh*per;
            dp = (uint2*)g_kc + bh*((size_t)KVLEN*HD/4) + rem;
        }
        else                       { j -= nKp; s = (const float4*)Wo + j; dp = (uint2*)g_wo + j; }
        float4 v = *s;
        __half2 h01 = __floats2half2_rn(v.x, v.y);
        __half2 h23 = __floats2half2_rn(v.z, v.w);
        uint2 o; o.x = *(uint32_t*)&h01; o.y = *(uint32_t*)&h23;
        *dp = o;
    }
}

// ---------------------------------------------------------------------------
// Past-V transpose (+fp16 round): [bh, kv, d] -> g_vt[bh, d, kv]
// ---------------------------------------------------------------------------
__global__ void vtrans(const float* __restrict__ pastV)
{
    __shared__ float t[32][33];
    const int bh  = blockIdx.x;
    const int kv0 = blockIdx.y * 32;
    const int d0  = blockIdx.z * 32;
    const int tx = threadIdx.x & 31, ty = threadIdx.x >> 5;
    const float* src = pastV + ((size_t)bh*PAST + kv0)*HD + d0;
    #pragma unroll
    for (int i = 0; i < 4; i++)
        t[ty + i*8][tx] = src[(size_t)(ty + i*8)*HD + tx];
    __syncthreads();
    __half* dst = g_vt + ((size_t)bh*HD + d0)*KVLEN + kv0;
    #pragma unroll
    for (int i = 0; i < 4; i++)
        dst[(size_t)(ty + i*8)*KVLEN + tx] = __float2half_rn(t[tx][ty + i*8]);
}

// ---------------------------------------------------------------------------
// GEMM mainloop: fp16 m16n8k16, 4 warps (2x2) of 64x64, BK=32 halves.
// ---------------------------------------------------------------------------
__device__ __forceinline__ void gemm_mainloop(
    const __half* __restrict__ Ag, const __half* __restrict__ Bg,
    float (&acc)[4][8][4])
{
    extern __shared__ char smc[];
    const uint32_t smbase = smem_u32(smc);

    const int tid  = threadIdx.x;
    const int lane = tid & 31;
    const int w    = tid >> 5;
    const int wm   = w & 1;
    const int wn   = w >> 1;

    #pragma unroll
    for (int mt = 0; mt < 4; mt++)
        #pragma unroll
        for (int nt = 0; nt < 8; nt++)
            #pragma unroll
            for (int c = 0; c < 4; c++) acc[mt][nt][c] = 0.f;

    // ldmatrix per-lane addresses (bytes within stage)
    const int arow = wm*64 + (lane & 7) + ((lane >> 3) & 1) * 8;
    const uint32_t aoff = (uint32_t)arow*SSTB + (uint32_t)(lane >> 4)*16u;
    const int brow = wn*64 + (lane & 7) + (lane >> 4) * 8;
    const uint32_t boff = (uint32_t)(128 + brow)*SSTB + (uint32_t)((lane >> 3) & 1)*16u;

    // staging: 8 cpasync16/thread/stage
    const int r0 = tid >> 2, c0h = (tid & 3) * 8;

    auto issue_stage = [&](int s, int k0){
        const uint32_t base = smbase + (uint32_t)s*STAGEB;
        const uint32_t bb   = base + (uint32_t)128*SSTB;
        #pragma unroll
        for (int j = 0; j < 4; j++) {
            const int row = r0 + j*32;
            cpasync16(base + (uint32_t)row*SSTB + c0h*2, Ag + (size_t)row*HID + k0 + c0h);
            cpasync16(bb   + (uint32_t)row*SSTB + c0h*2, Bg + (size_t)row*HID + k0 + c0h);
        }
    };

    #pragma unroll
    for (int s = 0; s < NSTAGE-1; s++) { issue_stage(s, s*BKH); CP_COMMIT(); }

    for (int kt = 0; kt < NKITER; kt++) {
        CP_WAIT2();
        __syncthreads();
        if (kt + NSTAGE-1 < NKITER) issue_stage((kt + NSTAGE-1) & 3, (kt + NSTAGE-1) * BKH);
        CP_COMMIT();

        const uint32_t Sbase = smbase + (uint32_t)(kt & 3)*STAGEB;
        const uint32_t Aaddr = Sbase + aoff;
        const uint32_t Baddr = Sbase + boff;
        #pragma unroll
        for (int ks = 0; ks < 2; ks++) {
            const uint32_t kkB = (uint32_t)ks * 32u;   // 16 halves
            uint32_t af[4][4], bf[8][2];
            #pragma unroll
            for (int mt = 0; mt < 4; mt++)
                ldsm4(Aaddr + (uint32_t)(mt*16)*SSTB + kkB,
                      af[mt][0], af[mt][1], af[mt][2], af[mt][3]);
            #pragma unroll
            for (int p = 0; p < 4; p++)
                ldsm4(Baddr + (uint32_t)(p*16)*SSTB + kkB,
                      bf[2*p][0], bf[2*p][1], bf[2*p+1][0], bf[2*p+1][1]);
            #pragma unroll
            for (int mt = 0; mt < 4; mt++)
                #pragma unroll
                for (int nt = 0; nt < 8; nt++)
                    mma16(acc[mt][nt], af[mt], bf[nt]);
        }
    }
    __syncthreads();
}

// ---------------------------------------------------------------------------
// QKV projection
// ---------------------------------------------------------------------------
__global__ void __launch_bounds__(128, 2) qkv_mma(
    const float* __restrict__ bq, const float* __restrict__ bk,
    const float* __restrict__ bv)
{
    const int m0  = blockIdx.x * BM;
    const int n0e = blockIdx.y * BN;
    const float* bias; int sel, nl0;
    if (n0e < 4096)      { bias = bq; sel = 0; nl0 = n0e; }
    else if (n0e < 5120) { bias = bk; sel = 1; nl0 = n0e - 4096; }
    else                 { bias = bv; sel = 2; nl0 = n0e - 5120; }

    float acc[4][8][4];
    gemm_mainloop(g_x + (size_t)m0*HID, g_wqkv + (size_t)n0e*HID, acc);

    const int lane = threadIdx.x & 31, w = threadIdx.x >> 5;
    const int wm = w & 1, wn = w >> 1;
    const int lq = lane >> 2, lr4 = lane & 3;

    #pragma unroll
    for (int mt = 0; mt < 4; mt++) {
        #pragma unroll
        for (int half = 0; half < 2; half++) {
            const int gm = m0 + wm*64 + mt*16 + lq + half*8;
            const int bb = gm >> 10, sq = gm & 1023;
            #pragma unroll
            for (int nt = 0; nt < 8; nt++) {
                const int nl = nl0 + wn*64 + nt*8 + lr4*2;
                const float2 bv2 = *reinterpret_cast<const float2*>(bias + nl);
                float vx = acc[mt][nt][half*2 + 0] + bv2.x;
                float vy = acc[mt][nt][half*2 + 1] + bv2.y;
                const int h = nl >> 7, d = nl & 127;
                if (sel == 0) {
                    __half2 hv = __floats2half2_rn(vx*QSCALE, vy*QSCALE);
                    *reinterpret_cast<__half2*>(
                        &g_qh[(((size_t)bb*NH + h)*QLEN + sq)*HD + d]) = hv;
                } else if (sel == 1) {
                    __half2 hv = __floats2half2_rn(vx, vy);
                    *reinterpret_cast<__half2*>(
                        &g_kc[(((size_t)bb*NKV + h)*KVLEN + PAST + sq)*HD + d]) = hv;
                } else {
                    __half* dst = &g_vt[(((size_t)bb*NKV + h)*HD + d)*(size_t)KVLEN + PAST + sq];
                    dst[0]     = __float2half_rn(vx);
                    dst[KVLEN] = __float2half_rn(vy);
                }
            }
        }
    }
}

// ---------------------------------------------------------------------------
// Output projection
// ---------------------------------------------------------------------------
__global__ void __launch_bounds__(128, 2) out_mma(
    const float* __restrict__ bo, float* __restrict__ out)
{
    const int m0 = blockIdx.x * BM;
    const int n0 = blockIdx.y * BN;

    float acc[4][8][4];
    gemm_mainloop(g_attn + (size_t)m0*HID, g_wo + (size_t)n0*HID, acc);

    const int lane = threadIdx.x & 31, w = threadIdx.x >> 5;
    const int wm = w & 1, wn = w >> 1;
    const int lq = lane >> 2, lr4 = lane & 3;

    #pragma unroll
    for (int mt = 0; mt < 4; mt++) {
        #pragma unroll
        for (int half = 0; half < 2; half++) {
            const int gm = m0 + wm*64 + mt*16 + lq + half*8;
            #pragma unroll
            for (int nt = 0; nt < 8; nt++) {
                const int gn = n0 + wn*64 + nt*8 + lr4*2;
                const float2 bv2 = *reinterpret_cast<const float2*>(bo + gn);
                float2 v;
                v.x = acc[mt][nt][half*2 + 0] + bv2.x;
                v.y = acc[mt][nt][half*2 + 1] + bv2.y;
                *reinterpret_cast<float2*>(out + (size_t)gm*HID + gn) = v;
            }
        }
    }
}

// ---------------------------------------------------------------------------
// Flash attention: fp16 m16n8k16, Q in registers, cp.async K/V, 2 CTAs/SM.
// ---------------------------------------------------------------------------
__global__ void __launch_bounds__(128, 2) attn_mma(
    const int* __restrict__ amask)
{
    extern __shared__ char smc[];
    __half* Kb = (__half*)smc;                 // [64][KSTH]  (also Q staging)
    __half* Vb = Kb + 64*KSTH;                 // [128][VSTH]
    __half* Ps = Vb + 128*VSTH;                // [64][VSTH]

    const uint32_t smKb = smem_u32(Kb);
    const uint32_t smVb = smem_u32(Vb);
    const uint32_t smPs = smem_u32(Ps);

    const int b = blockIdx.z, h = blockIdx.y, q0 = blockIdx.x * AQ;
    const int hkv = h >> 2;
    const int tid = threadIdx.x;
    const int lane = tid & 31, w = tid >> 5;
    const int lq = lane >> 2, lr4 = lane & 3;
    const int qrow = w*16 + lq;

    // A-operand lane pattern
    const int a_r = (lane & 7) + ((lane >> 3) & 1) * 8;
    const uint32_t a_cB = (uint32_t)(lane >> 4) * 16u;
    const uint32_t qstage = smKb + (uint32_t)(w*16 + a_r)*KSTB + a_cB;
    const uint32_t pfrag  = smPs + (uint32_t)(w*16 + a_r)*VSTB + a_cB;
    // B-operand lane pattern
    const int b_r = (lane & 7) + (lane >> 4) * 8;
    const uint32_t b_cB = (uint32_t)((lane >> 3) & 1) * 16u;
    const uint32_t kfrag = smKb + (uint32_t)b_r*KSTB + b_cB;
    const uint32_t vfrag = smVb + (uint32_t)b_r*VSTB + b_cB;

    const __half* Kg = g_kc + ((size_t)b*NKV + hkv)*(size_t)KVLEN*HD;
    const __half* Vg = g_vt + ((size_t)b*NKV + hkv)*(size_t)HD*KVLEN;
    const int*    mg = amask + (size_t)b * KVLEN;

    auto issue_K = [&](int kt){
        const __half* src = Kg + (size_t)kt*64*HD;
        #pragma unroll
        for (int i = 0; i < 8; i++){
            const int c = tid + i*128;
            const int row = c >> 4, colh = (c & 15) * 8;
            cpasync16(smKb + (uint32_t)row*KSTB + colh*2, src + (size_t)row*HD + colh);
        }
    };
    auto issue_V = [&](int kt){
        const __half* src = Vg + kt*64;
        #pragma unroll
        for (int i = 0; i < 8; i++){
            const int c = tid + i*128;
            const int row = c >> 3, colh = (c & 7) * 8;
            cpasync16(smVb + (uint32_t)row*VSTB + colh*2, src + (size_t)row*KVLEN + colh);
        }
    };

    // Stage Q (already scaled+rounded in g_qh) through Kb, ldsm to registers.
    {
        const __half* Qg = g_qh + (((size_t)b*NH + h)*QLEN + q0) * HD;
        #pragma unroll
        for (int i = 0; i < 8; i++) {
            const int c = tid + i*128;
            const int row = c >> 4, colh = (c & 15) * 8;
            *reinterpret_cast<float4*>(Kb + row*KSTH + colh) =
                *reinterpret_cast<const float4*>(Qg + (size_t)row*HD + colh);
        }
    }
    __syncthreads();
    uint32_t qf[8][4];
    #pragma unroll
    for (int ks = 0; ks < 8; ks++)
        ldsm4(qstage + (uint32_t)ks*32u, qf[ks][0], qf[ks][1], qf[ks][2], qf[ks][3]);
    __syncthreads();

    issue_K(0); CP_COMMIT();

    float oacc[16][4];
    #pragma unroll
    for (int d = 0; d < 16; d++)
        #pragma unroll
        for (int c = 0; c < 4; c++) oacc[d][c] = 0.f;
    float m0 = -3.0e38f, m1 = -3.0e38f, l0 = 0.f, l1 = 0.f;

    for (int kt = 0; kt < 32; kt++) {
        CP_WAIT0();
        __syncthreads();
        issue_V(kt); CP_COMMIT();

        // S = Q @ K^T  (8 k16-steps over HD=128)
        float sacc[8][4];
        #pragma unroll
        for (int nt = 0; nt < 8; nt++)
            #pragma unroll
            for (int c = 0; c < 4; c++) sacc[nt][c] = 0.f;
        #pragma unroll
        for (int ks = 0; ks < 8; ks++) {
            const uint32_t kkB = (uint32_t)ks * 32u;
            uint32_t bf[8][2];
            #pragma unroll
            for (int p = 0; p < 4; p++)
                ldsm4(kfrag + (uint32_t)(p*16)*KSTB + kkB,
                      bf[2*p][0], bf[2*p][1], bf[2*p+1][0], bf[2*p+1][1]);
            #pragma unroll
            for (int nt = 0; nt < 8; nt++)
                mma16(sacc[nt], qf[ks], bf[nt]);
        }
        __syncthreads();
        if (kt < 31) { issue_K(kt+1); CP_COMMIT(); }

        // mask + online softmax
        float tmax0 = -3.0e38f, tmax1 = -3.0e38f;
        #pragma unroll
        for (int nt = 0; nt < 8; nt++) {
            const int ci = kt*64 + nt*8 + lr4*2;
            const float b0 = (mg[ci]   == 0) ? 0.f : NEGBIG;
            const float b1 = (mg[ci+1] == 0) ? 0.f : NEGBIG;
            sacc[nt][0] += b0; sacc[nt][1] += b1;
            sacc[nt][2] += b0; sacc[nt][3] += b1;
            tmax0 = fmaxf(tmax0, fmaxf(sacc[nt][0], sacc[nt][1]));
            tmax1 = fmaxf(tmax1, fmaxf(sacc[nt][2], sacc[nt][3]));
        }
        tmax0 = fmaxf(tmax0, __shfl_xor_sync(0xFFFFFFFFu, tmax0, 1));
        tmax0 = fmaxf(tmax0, __shfl_xor_sync(0xFFFFFFFFu, tmax0, 2));
        tmax1 = fmaxf(tmax1, __shfl_xor_sync(0xFFFFFFFFu, tmax1, 1));
        tmax1 = fmaxf(tmax1, __shfl_xor_sync(0xFFFFFFFFu, tmax1, 2));
        const float mn0 = fmaxf(m0, tmax0), mn1 = fmaxf(m1, tmax1);
        const float sc0 = __expf(m0 - mn0), sc1 = __expf(m1 - mn1);
        float sum0 = 0.f, sum1 = 0.f;
        #pragma unroll
        for (int nt = 0; nt < 8; nt++) {
            const float p00 = __expf(sacc[nt][0] - mn0);
            const float p01 = __expf(sacc[nt][1] - mn0);
            const float p10 = __expf(sacc[nt][2] - mn1);
            const float p11 = __expf(sacc[nt][3] - mn1);
            sum0 += p00 + p01; sum1 += p10 + p11;
            *reinterpret_cast<__half2*>(Ps + qrow*VSTH + nt*8 + lr4*2) =
                __floats2half2_rn(p00, p01);
            *reinterpret_cast<__half2*>(Ps + (qrow+8)*VSTH + nt*8 + lr4*2) =
                __floats2half2_rn(p10, p11);
        }
        sum0 += __shfl_xor_sync(0xFFFFFFFFu, sum0, 1);
        sum0 += __shfl_xor_sync(0xFFFFFFFFu, sum0, 2);
        sum1 += __shfl_xor_sync(0xFFFFFFFFu, sum1, 1);
        sum1 += __shfl_xor_sync(0xFFFFFFFFu, sum1, 2);
        l0 = l0*sc0 + sum0; l1 = l1*sc1 + sum1;
        m0 = mn0; m1 = mn1;
        #pragma unroll
        for (int d = 0; d < 16; d++) {
            oacc[d][0] *= sc0; oacc[d][1] *= sc0;
            oacc[d][2] *= sc1; oacc[d][3] *= sc1;
        }
        __syncwarp();

        if (kt < 31) { CP_WAIT1(); } else { CP_WAIT0(); }
        __syncthreads();

        // O += P @ V  (4 k16-steps over kv=64)
        #pragma unroll
        for (int ks = 0; ks < 4; ks++) {
            const uint32_t kkB = (uint32_t)ks * 32u;
            uint32_t af[4];
            ldsm4(pfrag + kkB, af[0], af[1], af[2], af[3]);
            #pragma unroll
            for (int p = 0; p < 8; p++) {
                uint32_t bf0, bf1, bf2, bf3;
                ldsm4(vfrag + (uint32_t)(p*16)*VSTB + kkB, bf0, bf1, bf2, bf3);
                uint32_t bfa[2] = { bf0, bf1 };
                uint32_t bfb[2] = { bf2, bf3 };
                mma16(oacc[2*p],     af, bfa);
                mma16(oacc[2*p + 1], af, bfb);
            }
        }
    }

    // normalize + write g_attn (half)
    const float inv0 = 1.f / l0, inv1 = 1.f / l1;
    __half* orow0 = g_attn + ((size_t)(b*QLEN + q0 + w*16 + lq))*HID + h*HD;
    __half* orow1 = orow0 + (size_t)8*HID;
    #pragma unroll
    for (int d = 0; d < 16; d++) {
        *reinterpret_cast<__half2*>(orow0 + d*8 + lr4*2) =
            __floats2half2_rn(oacc[d][0]*inv0, oacc[d][1]*inv0);
        *reinterpret_cast<__half2*>(orow1 + d*8 + lr4*2) =
            __floats2half2_rn(oacc[d][2]*inv1, oacc[d][3]*inv1);
    }
}

// ---------------------------------------------------------------------------
extern "C" void kernel_launch(void* const* d_in, const int* in_sizes, int n_in,
                              void* d_out, int out_size)
{
    const float* hs = (const float*)d_in[0];
    const float* pk = (const float*)d_in[1];
    const float* pv = (const float*)d_in[2];
    const int*   mk = (const int*)  d_in[3];
    const float* Wq = (const float*)d_in[4];
    const float* bq = (const float*)d_in[5];
    const float* Wk = (const float*)d_in[6];
    const float* bk = (const float*)d_in[7];
    const float* Wv = (const float*)d_in[8];
    const float* bv = (const float*)d_in[9];
    const float* Wo = (const float*)d_in[10];
    const float* bo = (const float*)d_in[11];
    float* out = (float*)d_out;

    cudaFuncSetAttribute(qkv_mma, cudaFuncAttributeMaxDynamicSharedMemorySize, GSMEM);
    cudaFuncSetAttribute(out_mma, cudaFuncAttributeMaxDynamicSharedMemorySize, GSMEM);
    cudaFuncSetAttribute(attn_mma, cudaFuncAttributeMaxDynamicSharedMemorySize, ATTN_SM_BYTES);

    cvt_all<<<2048, 256>>>(hs, Wq, Wk, Wv, Wo, pk);

    dim3 gv(NB*NKV, PAST/32, HD/32);
    vtrans<<<gv, 256>>>(pv);

    dim3 g1(MROWS/BM, 6144/BN);           // 32 x 48
    qkv_mma<<<g1, 128, GSMEM>>>(bq, bk, bv);

    dim3 g2(QLEN/AQ, NH, NB);             // 16 x 32 x 4
    attn_mma<<<g2, 128, ATTN_SM_BYTES>>>(mk);

    dim3 g3(MROWS/BM, HID/BN);            // 32 x 32
    out_mma<<<g3, 128, GSMEM>>>(bo, out);
}